// round 10
// baseline (speedup 1.0000x reference)
#include <cuda_runtime.h>
#include <math.h>
#include <stdint.h>

#define CC 256
#define NN 2048
#define DD 65536
#define NE 64
#define ROUT 256
#define DECAYv 0.999f
#define GAMv 4.8828125e-7f
#define COMMITv 0.25f

__device__ float g_M[CC*CC];
__device__ float g_G[NE*CC];
__device__ float g_A[NE*CC];
__device__ float g_Q[NE*NE];
__device__ float g_CG[NE*NE];
__device__ double g_cnormd[NE], g_bcd[NE], g_bbd;
__device__ float g_s[NE];
__device__ float g_Wtb[CC];
__device__ float g_xsum[CC];
__device__ double g_accd[4];      // 0:S0  1:S1a  2:p  3:quad
__device__ float g_Y[NN*CC];
__device__ float g_resp[NN*NE];
__device__ int   g_cnt[NE];
__device__ int   g_tokn[NE*NN];
__device__ float g_tokr[NE*NN];
__device__ float g_Cnew[NE*DD];

__device__ __forceinline__ void mma8(float* c, const uint32_t* a, const uint32_t* b) {
    asm volatile("mma.sync.aligned.m16n8k8.row.col.f32.tf32.tf32.f32 "
        "{%0,%1,%2,%3}, {%4,%5,%6,%7}, {%8,%9}, {%0,%1,%2,%3};"
        : "+f"(c[0]), "+f"(c[1]), "+f"(c[2]), "+f"(c[3])
        : "r"(a[0]), "r"(a[1]), "r"(a[2]), "r"(a[3]), "r"(b[0]), "r"(b[1]));
}
__device__ __forceinline__ uint32_t fb(float x) { return __float_as_uint(x); }
__device__ __forceinline__ void hilo(float v, uint32_t& h, uint32_t& l) {
    uint32_t hb = __float_as_uint(v) & 0xFFFFE000u;
    h = hb;
    l = fb(v - __uint_as_float(hb));
}

// ================= zero =================
__global__ void k_zero(float* __restrict__ out) {
    int i = blockIdx.x * 256 + threadIdx.x;
    if (i < NN*ROUT) out[i] = 0.f;
    if (i < CC*CC) g_M[i] = 0.f;
    if (i < NE*CC) { g_G[i]=0.f; g_A[i]=0.f; }
    if (i < NE*NE) { g_Q[i]=0.f; g_CG[i]=0.f; }
    if (i < CC) { g_Wtb[i] = 0.f; g_xsum[i] = 0.f; }
    if (i < NE) { g_cnormd[i]=0.0; g_bcd[i]=0.0; g_s[i]=0.f; g_cnt[i]=0; }
    if (i < 4) g_accd[i] = 0.0;
    if (i == 4) g_bbd = 0.0;
}

// ================= phase 1: gram(M, sym, 96) | centW (128) | Y (128) =================
__global__ void __launch_bounds__(256) k_p1(const float* __restrict__ W,
                                            const float* __restrict__ cents,
                                            const float* __restrict__ bvec,
                                            const float* __restrict__ x,
                                            const float* __restrict__ pw1) {
    __shared__ __align__(16) char smp[43008];
    int b = blockIdx.x;
    int tid=threadIdx.x, warp=tid>>5, lane=tid&31, gid=lane>>2, tig=lane&3;

    if (b < 96) {
        // ---- gram: M = W^T W, symmetric: tiles (0,0),(128,128),(0,128)+mirror ----
        float (*Ws)[260] = (float (*)[260])smp;
        int wm = warp>>2, wn = warp&3;
        int tt = b % 3;
        int i0 = (tt == 1) ? 128 : 0;
        int j0 = (tt == 0) ? 0 : 128;
        int d0 = (b / 3) * 2048;
        float acc[4][4][4];
#pragma unroll
        for (int mt=0;mt<4;mt++)
#pragma unroll
            for (int nt=0;nt<4;nt++)
#pragma unroll
                for (int q=0;q<4;q++) acc[mt][nt][q]=0.f;

        for (int ch=0; ch<64; ch++) {
            int drow = d0 + ch*32;
#pragma unroll
            for (int l=0;l<8;l++) {
                int idx = tid + l*256;
                int row = idx>>6, c4 = (idx&63)*4;
                float4 v = *(const float4*)(W + (size_t)(drow+row)*CC + c4);
                Ws[row][c4]=v.x; Ws[row][c4+1]=v.y; Ws[row][c4+2]=v.z; Ws[row][c4+3]=v.w;
            }
            __syncthreads();
#pragma unroll
            for (int k8=0;k8<4;k8++) {
                int kb = k8*8;
                uint32_t a[4][4];
#pragma unroll
                for (int mt=0;mt<4;mt++) {
                    int ib = i0 + wm*64 + mt*16 + gid;
                    a[mt][0]=fb(Ws[kb+tig][ib]);   a[mt][1]=fb(Ws[kb+tig][ib+8]);
                    a[mt][2]=fb(Ws[kb+tig+4][ib]); a[mt][3]=fb(Ws[kb+tig+4][ib+8]);
                }
#pragma unroll
                for (int nt=0;nt<4;nt++) {
                    int jb = j0 + wn*32 + nt*8 + gid;
                    uint32_t bv[2] = { fb(Ws[kb+tig][jb]), fb(Ws[kb+tig+4][jb]) };
#pragma unroll
                    for (int mt=0;mt<4;mt++) mma8(acc[mt][nt], a[mt], bv);
                }
            }
            __syncthreads();
        }
#pragma unroll
        for (int mt=0;mt<4;mt++)
#pragma unroll
            for (int nt=0;nt<4;nt++) {
                int i = i0 + wm*64 + mt*16 + gid;
                int j = j0 + wn*32 + nt*8 + 2*tig;
                atomicAdd(&g_M[i*CC+j],       acc[mt][nt][0]);
                atomicAdd(&g_M[i*CC+j+1],     acc[mt][nt][1]);
                atomicAdd(&g_M[(i+8)*CC+j],   acc[mt][nt][2]);
                atomicAdd(&g_M[(i+8)*CC+j+1], acc[mt][nt][3]);
                if (tt == 2) {
                    atomicAdd(&g_M[j*CC+i],       acc[mt][nt][0]);
                    atomicAdd(&g_M[(j+1)*CC+i],   acc[mt][nt][1]);
                    atomicAdd(&g_M[j*CC+i+8],     acc[mt][nt][2]);
                    atomicAdd(&g_M[(j+1)*CC+i+8], acc[mt][nt][3]);
                }
            }
    } else if (b < 224) {
        // ---- centW: G = Cents@W (FULL hi/lo) + CG (hi/lo) + cnorm/bc/Wtb/bb ----
        float (*Cs)[36]  = (float (*)[36])smp;
        float (*Ws)[260] = (float (*)[260])(smp + 9216);
        float* bs        = (float*)(smp + 9216 + 33280);
        int blk = b - 96;
        int d0 = blk * 512;
        float accG[4][4][4], accCG[4][4];
#pragma unroll
        for (int mt=0;mt<4;mt++) {
#pragma unroll
            for (int nt=0;nt<4;nt++)
#pragma unroll
                for (int q=0;q<4;q++) accG[mt][nt][q]=0.f;
#pragma unroll
            for (int q=0;q<4;q++) accCG[mt][q]=0.f;
        }
        float accWtb=0.f, accCN=0.f, accBC=0.f, accBB=0.f;

        for (int ch=0; ch<16; ch++) {
            int dbase = d0 + ch*32;
#pragma unroll
            for (int l=0;l<2;l++) {
                int idx = tid + l*256;
                int e = idx>>3, q = (idx&7)*4;
                float4 v = *(const float4*)(cents + (size_t)e*DD + dbase + q);
                Cs[e][q]=v.x; Cs[e][q+1]=v.y; Cs[e][q+2]=v.z; Cs[e][q+3]=v.w;
            }
#pragma unroll
            for (int l=0;l<8;l++) {
                int idx = tid + l*256;
                int row = idx>>6, q = (idx&63)*4;
                float4 v = *(const float4*)(W + (size_t)(dbase+row)*CC + q);
                Ws[row][q]=v.x; Ws[row][q+1]=v.y; Ws[row][q+2]=v.z; Ws[row][q+3]=v.w;
            }
            if (tid < 32) bs[tid] = bvec[dbase + tid];
            __syncthreads();
            {
                float aw = 0.f;
                for (int k=0;k<32;k++) aw += bs[k]*Ws[k][tid];
                accWtb += aw;
            }
            if (tid < 64) {
                float cn=0.f, bc=0.f;
                for (int k=0;k<32;k++) { float c=Cs[tid][k]; cn+=c*c; bc+=c*bs[k]; }
                accCN += cn; accBC += bc;
            }
            if (tid == 64) {
                float sb=0.f;
                for (int k=0;k<32;k++) sb += bs[k]*bs[k];
                accBB += sb;
            }
#pragma unroll
            for (int k8=0;k8<4;k8++) {
                int kb = k8*8;
                uint32_t ah[4][4], al[4][4];
#pragma unroll
                for (int mt=0;mt<4;mt++) {
                    int e = mt*16 + gid;
                    hilo(Cs[e][kb+tig],     ah[mt][0], al[mt][0]);
                    hilo(Cs[e+8][kb+tig],   ah[mt][1], al[mt][1]);
                    hilo(Cs[e][kb+tig+4],   ah[mt][2], al[mt][2]);
                    hilo(Cs[e+8][kb+tig+4], ah[mt][3], al[mt][3]);
                }
#pragma unroll
                for (int nt=0;nt<4;nt++) {
                    int c = warp*32 + nt*8 + gid;
                    uint32_t bh[2], bl[2];
                    hilo(Ws[kb+tig][c],   bh[0], bl[0]);
                    hilo(Ws[kb+tig+4][c], bh[1], bl[1]);
#pragma unroll
                    for (int mt=0;mt<4;mt++) {
                        mma8(accG[mt][nt], ah[mt], bh);
                        mma8(accG[mt][nt], ah[mt], bl);
                        mma8(accG[mt][nt], al[mt], bh);
                    }
                }
                {
                    int n0q = warp*8 + gid;
                    uint32_t bh[2], bl[2];
                    hilo(Cs[n0q][kb+tig],   bh[0], bl[0]);
                    hilo(Cs[n0q][kb+tig+4], bh[1], bl[1]);
#pragma unroll
                    for (int mt=0;mt<4;mt++) {
                        mma8(accCG[mt], ah[mt], bh);
                        mma8(accCG[mt], ah[mt], bl);
                        mma8(accCG[mt], al[mt], bh);
                    }
                }
            }
            __syncthreads();
        }
#pragma unroll
        for (int mt=0;mt<4;mt++) {
#pragma unroll
            for (int nt=0;nt<4;nt++) {
                int e = mt*16 + gid;
                int c = warp*32 + nt*8 + 2*tig;
                atomicAdd(&g_G[e*CC+c],       accG[mt][nt][0]);
                atomicAdd(&g_G[e*CC+c+1],     accG[mt][nt][1]);
                atomicAdd(&g_G[(e+8)*CC+c],   accG[mt][nt][2]);
                atomicAdd(&g_G[(e+8)*CC+c+1], accG[mt][nt][3]);
            }
            int e = mt*16 + gid;
            int n = warp*8 + 2*tig;
            atomicAdd(&g_CG[e*NE+n],       accCG[mt][0]);
            atomicAdd(&g_CG[e*NE+n+1],     accCG[mt][1]);
            atomicAdd(&g_CG[(e+8)*NE+n],   accCG[mt][2]);
            atomicAdd(&g_CG[(e+8)*NE+n+1], accCG[mt][3]);
        }
        atomicAdd(&g_Wtb[tid], accWtb);
        if (tid < 64) { atomicAdd(&g_cnormd[tid], (double)accCN); atomicAdd(&g_bcd[tid], (double)accBC); }
        if (tid == 64) atomicAdd(&g_bbd, (double)accBB);
    } else {
        // ---- Y = X @ pw1^T  (hi/lo) ----
        float (*Xs)[36] = (float (*)[36])smp;
        float (*Bs)[36] = (float (*)[36])(smp + 9216);
        int yb = b - 224;
        int tok0 = (yb >> 2) * 64;
        int colgrp = yb & 3;
        const float* src = pw1 + (size_t)colgrp * 64 * CC;
        int wm = warp>>2, wn = warp&3;
        float acc[2][2][4];
#pragma unroll
        for (int mt=0;mt<2;mt++)
#pragma unroll
            for (int nt=0;nt<2;nt++)
#pragma unroll
                for (int q=0;q<4;q++) acc[mt][nt][q]=0.f;

        for (int ch=0; ch<8; ch++) {
            int kc = ch*32;
#pragma unroll
            for (int l=0;l<2;l++) {
                int idx = tid + l*256;
                int row = idx>>3, q = (idx&7)*4;
                float4 v = *(const float4*)(x + (size_t)(tok0+row)*CC + kc + q);
                Xs[row][q]=v.x; Xs[row][q+1]=v.y; Xs[row][q+2]=v.z; Xs[row][q+3]=v.w;
                float4 w = *(const float4*)(src + (size_t)row*CC + kc + q);
                Bs[row][q]=w.x; Bs[row][q+1]=w.y; Bs[row][q+2]=w.z; Bs[row][q+3]=w.w;
            }
            __syncthreads();
#pragma unroll
            for (int k8=0;k8<4;k8++) {
                int kb = k8*8;
                uint32_t ah[2][4], al[2][4], bh[2][2], bl[2][2];
#pragma unroll
                for (int mt=0;mt<2;mt++) {
                    int m0 = wm*32 + mt*16 + gid;
                    hilo(Xs[m0][kb+tig],     ah[mt][0], al[mt][0]);
                    hilo(Xs[m0+8][kb+tig],   ah[mt][1], al[mt][1]);
                    hilo(Xs[m0][kb+tig+4],   ah[mt][2], al[mt][2]);
                    hilo(Xs[m0+8][kb+tig+4], ah[mt][3], al[mt][3]);
                }
#pragma unroll
                for (int nt=0;nt<2;nt++) {
                    int nl = wn*16 + nt*8 + gid;
                    hilo(Bs[nl][kb+tig],   bh[nt][0], bl[nt][0]);
                    hilo(Bs[nl][kb+tig+4], bh[nt][1], bl[nt][1]);
                }
#pragma unroll
                for (int mt=0;mt<2;mt++)
#pragma unroll
                    for (int nt=0;nt<2;nt++) {
                        mma8(acc[mt][nt], ah[mt], bh[nt]);
                        mma8(acc[mt][nt], ah[mt], bl[nt]);
                        mma8(acc[mt][nt], al[mt], bh[nt]);
                    }
            }
            __syncthreads();
        }
#pragma unroll
        for (int mt=0;mt<2;mt++)
#pragma unroll
            for (int nt=0;nt<2;nt++) {
                int col = colgrp*64 + wn*16 + nt*8 + 2*tig;
#pragma unroll
                for (int rr=0;rr<2;rr++) {
                    int tok = tok0 + wm*32 + mt*16 + gid + rr*8;
                    g_Y[(size_t)tok*CC + col]   = acc[mt][nt][rr*2];
                    g_Y[(size_t)tok*CC + col+1] = acc[mt][nt][rr*2+1];
                }
            }
    }
}

// ================= phase 2 (32-token tiles): S0 from X@M | xG+softmax+binning =================
__global__ void __launch_bounds__(256) k_big2(const float* __restrict__ x,
                                              const float* __restrict__ u) {
    __shared__ __align__(16) char smp[22528];
    float (*Xs)[36] = (float (*)[36])smp;              // 32x36 = 4608
    float (*Bs)[36] = (float (*)[36])(smp + 4608);     // 64x36 = 9216
    float (*xgs)[68] = (float (*)[68])(smp + 13824);   // 32x68 = 8704
    float* red = (float*)(smp + 13824);
    int b = blockIdx.x;
    int tid=threadIdx.x, warp=tid>>5, lane=tid&31, gid=lane>>2, tig=lane&3;
    int wm = warp>>2, wn = warp&3;
    int tok0, colgrp, mode;
    const float* src;
    if (b < 256) { tok0 = (b>>2)*32; colgrp = b&3; src = g_M + (size_t)colgrp*64*CC; mode=0; }
    else         { tok0 = (b-256)*32; colgrp = 0;  src = g_G; mode=1; }
    float acc[2][4];
#pragma unroll
    for (int nt=0;nt<2;nt++)
#pragma unroll
        for (int q=0;q<4;q++) acc[nt][q]=0.f;

    for (int ch=0; ch<8; ch++) {
        int kc = ch*32;
        {
            int row = tid>>3, q = (tid&7)*4;
            float4 v = *(const float4*)(x + (size_t)(tok0+row)*CC + kc + q);
            Xs[row][q]=v.x; Xs[row][q+1]=v.y; Xs[row][q+2]=v.z; Xs[row][q+3]=v.w;
        }
#pragma unroll
        for (int l=0;l<2;l++) {
            int idx = tid + l*256;
            int row = idx>>3, q = (idx&7)*4;
            float4 w = *(const float4*)(src + (size_t)row*CC + kc + q);
            Bs[row][q]=w.x; Bs[row][q+1]=w.y; Bs[row][q+2]=w.z; Bs[row][q+3]=w.w;
        }
        __syncthreads();
#pragma unroll
        for (int k8=0;k8<4;k8++) {
            int kb = k8*8;
            uint32_t ah[4], al[4], bh[2][2], bl[2][2];
            int m0 = wm*16 + gid;
            hilo(Xs[m0][kb+tig],     ah[0], al[0]);
            hilo(Xs[m0+8][kb+tig],   ah[1], al[1]);
            hilo(Xs[m0][kb+tig+4],   ah[2], al[2]);
            hilo(Xs[m0+8][kb+tig+4], ah[3], al[3]);
#pragma unroll
            for (int nt=0;nt<2;nt++) {
                int nl = wn*16 + nt*8 + gid;
                hilo(Bs[nl][kb+tig],   bh[nt][0], bl[nt][0]);
                hilo(Bs[nl][kb+tig+4], bh[nt][1], bl[nt][1]);
            }
#pragma unroll
            for (int nt=0;nt<2;nt++) {
                mma8(acc[nt], ah, bh[nt]);
                mma8(acc[nt], ah, bl[nt]);
                mma8(acc[nt], al, bh[nt]);
            }
        }
        __syncthreads();
    }
    if (mode == 0) {
        float s0 = 0.f;
#pragma unroll
        for (int nt=0;nt<2;nt++) {
            int col = colgrp*64 + wn*16 + nt*8 + 2*tig;
            int m0 = wm*16 + gid;
            s0 += acc[nt][0] * x[(size_t)(tok0+m0)*CC + col];
            s0 += acc[nt][1] * x[(size_t)(tok0+m0)*CC + col+1];
            s0 += acc[nt][2] * x[(size_t)(tok0+m0+8)*CC + col];
            s0 += acc[nt][3] * x[(size_t)(tok0+m0+8)*CC + col+1];
        }
        red[tid] = s0; __syncthreads();
        for (int s=128;s>=1;s>>=1) { if (tid<s) red[tid]+=red[tid+s]; __syncthreads(); }
        if (tid == 0) atomicAdd(&g_accd[0], (double)red[0]);
        return;
    }
    // mode 1: stage xG, fused softmax/S1a/binning (32 tokens)
#pragma unroll
    for (int nt=0;nt<2;nt++) {
        int col = wn*16 + nt*8 + 2*tig;
        int m0 = wm*16 + gid;
        xgs[m0][col]     = acc[nt][0];
        xgs[m0][col+1]   = acc[nt][1];
        xgs[m0+8][col]   = acc[nt][2];
        xgs[m0+8][col+1] = acc[nt][3];
    }
    __syncthreads();
    float cn0 = (float)g_cnormd[lane], cn1 = (float)g_cnormd[lane+32];
    float bc0 = (float)g_bcd[lane],    bc1 = (float)g_bcd[lane+32];
    float s1acc = 0.f;
    for (int k=0;k<4;k++) {
        int lt = warp*4 + k;
        size_t n = tok0 + lt;
        float xg0 = xgs[lt][lane]    + bc0;
        float xg1 = xgs[lt][lane+32] + bc1;
        float l0 = 2.f*xg0 - cn0 - logf(-logf(u[n*NE+lane]));
        float l1 = 2.f*xg1 - cn1 - logf(-logf(u[n*NE+lane+32]));
        float m = fmaxf(l0, l1);
#pragma unroll
        for (int o=16;o>=1;o>>=1) m = fmaxf(m, __shfl_xor_sync(0xffffffffu, m, o));
        float ex0 = expf(l0 - m), ex1 = expf(l1 - m);
        float S = ex0 + ex1;
#pragma unroll
        for (int o=16;o>=1;o>>=1) S += __shfl_xor_sync(0xffffffffu, S, o);
        float r0 = ex0 / S, r1 = ex1 / S;
        g_resp[n*NE+lane]    = r0;
        g_resp[n*NE+lane+32] = r1;
        float s1 = r0*xg0 + r1*xg1;
#pragma unroll
        for (int o=16;o>=1;o>>=1) s1 += __shfl_xor_sync(0xffffffffu, s1, o);
        if (lane == 0) s1acc += s1;
        if (r0 > 1e-9f) {
            int p = atomicAdd(&g_cnt[lane], 1);
            g_tokn[lane*NN+p] = (int)n; g_tokr[lane*NN+p] = r0;
        }
        if (r1 > 1e-9f) {
            int p = atomicAdd(&g_cnt[lane+32], 1);
            g_tokn[(lane+32)*NN+p] = (int)n; g_tokr[(lane+32)*NN+p] = r1;
        }
    }
    if (lane == 0) atomicAdd(&g_accd[1], (double)s1acc);
}

// ================= A=R^T X (plain), Q=R^T R (hi/lo), s, xsum  (32 tokens/blk) =================
__global__ void __launch_bounds__(256) k_RX(const float* __restrict__ x) {
    __shared__ float Rs[32][68];
    __shared__ float Xs[32][260];
    int tid=threadIdx.x, warp=tid>>5, lane=tid&31, gid=lane>>2, tig=lane&3;
    int nb = blockIdx.x * 32;
    float accA[4][4][4], accQ[4][4];
#pragma unroll
    for (int mt=0;mt<4;mt++) {
#pragma unroll
        for (int nt=0;nt<4;nt++)
#pragma unroll
            for (int q=0;q<4;q++) accA[mt][nt][q]=0.f;
#pragma unroll
        for (int q=0;q<4;q++) accQ[mt][q]=0.f;
    }
    float sp=0.f, xsacc=0.f;

#pragma unroll
    for (int l=0;l<8;l++) {
        int idx = tid + l*256;
        int row = idx>>6, e2 = idx&63;
        Rs[row][e2] = g_resp[(size_t)(nb+row)*NE + e2];
    }
#pragma unroll
    for (int l=0;l<8;l++) {
        int idx = tid + l*256;
        int row = idx>>6, q = (idx&63)*4;
        float4 v = *(const float4*)(x + (size_t)(nb+row)*CC + q);
        Xs[row][q]=v.x; Xs[row][q+1]=v.y; Xs[row][q+2]=v.z; Xs[row][q+3]=v.w;
    }
    __syncthreads();
    if (tid < 64) {
        for (int k=0;k<32;k++) sp += Rs[k][tid];
    }
    for (int k=0;k<32;k++) xsacc += Xs[k][tid];
#pragma unroll
    for (int k8=0;k8<4;k8++) {
        int kb = k8*8;
        uint32_t am[4][4], amh[4][4], aml[4][4];
#pragma unroll
        for (int mt=0;mt<4;mt++) {
            int m0 = mt*16;
            float v0 = Rs[kb+tig][m0+gid],   v1 = Rs[kb+tig][m0+gid+8];
            float v2 = Rs[kb+tig+4][m0+gid], v3 = Rs[kb+tig+4][m0+gid+8];
            am[mt][0]=fb(v0); am[mt][1]=fb(v1); am[mt][2]=fb(v2); am[mt][3]=fb(v3);
            hilo(v0, amh[mt][0], aml[mt][0]); hilo(v1, amh[mt][1], aml[mt][1]);
            hilo(v2, amh[mt][2], aml[mt][2]); hilo(v3, amh[mt][3], aml[mt][3]);
        }
#pragma unroll
        for (int nt=0;nt<4;nt++) {
            int c = warp*32 + nt*8 + gid;
            uint32_t bx[2] = { fb(Xs[kb+tig][c]), fb(Xs[kb+tig+4][c]) };
#pragma unroll
            for (int mt=0;mt<4;mt++) mma8(accA[mt][nt], am[mt], bx);
        }
        {
            int eq = warp*8 + gid;
            uint32_t bqh[2], bql[2];
            hilo(Rs[kb+tig][eq],   bqh[0], bql[0]);
            hilo(Rs[kb+tig+4][eq], bqh[1], bql[1]);
#pragma unroll
            for (int mt=0;mt<4;mt++) {
                mma8(accQ[mt], amh[mt], bqh);
                mma8(accQ[mt], amh[mt], bql);
                mma8(accQ[mt], aml[mt], bqh);
            }
        }
    }
#pragma unroll
    for (int mt=0;mt<4;mt++) {
#pragma unroll
        for (int nt=0;nt<4;nt++) {
            int e = mt*16 + gid;
            int c = warp*32 + nt*8 + 2*tig;
            atomicAdd(&g_A[e*CC+c],        accA[mt][nt][0]);
            atomicAdd(&g_A[e*CC+c+1],      accA[mt][nt][1]);
            atomicAdd(&g_A[(e+8)*CC+c],    accA[mt][nt][2]);
            atomicAdd(&g_A[(e+8)*CC+c+1],  accA[mt][nt][3]);
        }
        int e = mt*16 + gid;
        int eq = warp*8 + 2*tig;
        atomicAdd(&g_Q[e*NE+eq],       accQ[mt][0]);
        atomicAdd(&g_Q[e*NE+eq+1],     accQ[mt][1]);
        atomicAdd(&g_Q[(e+8)*NE+eq],   accQ[mt][2]);
        atomicAdd(&g_Q[(e+8)*NE+eq+1], accQ[mt][3]);
    }
    if (tid < 64) atomicAdd(&g_s[tid], sp);
    atomicAdd(&g_xsum[tid], xsacc);
}

// ================= Cnew (512 blks) | loss contractions (64 blks) =================
__global__ void __launch_bounds__(256) k_cnew(const float* __restrict__ W,
                                              const float* __restrict__ cents,
                                              const float* __restrict__ bvec) {
    int tid=threadIdx.x, warp=tid>>5, lane=tid&31, gid=lane>>2, tig=lane&3;
    if (blockIdx.x >= 512) {
        // ---- loss contractions, block e ----
        int e = blockIdx.x - 512;
        __shared__ float As[256];
        __shared__ float red[256];
        As[tid] = g_A[e*CC + tid];
        __syncthreads();
        float uv = 0.f;
        for (int e2=0;e2<NE;e2++) uv += g_Q[e*NE+e2] * g_A[e2*CC + tid];
        float am = 0.f;
        for (int c=0;c<CC;c++) am += As[c] * g_M[c*CC + tid];
        float a = As[tid];
        float ge = g_G[e*CC + tid];
        float wtb = g_Wtb[tid];

        float r1, r2, r3, r4, r5, r6;
        red[tid] = am*a; __syncthreads();
        for (int s=128;s>=1;s>>=1) { if (tid<s) red[tid]+=red[tid+s]; __syncthreads(); }
        r1 = red[0]; __syncthreads();
        red[tid] = a*wtb; __syncthreads();
        for (int s=128;s>=1;s>>=1) { if (tid<s) red[tid]+=red[tid+s]; __syncthreads(); }
        r2 = red[0]; __syncthreads();
        red[tid] = ge*uv; __syncthreads();
        for (int s=128;s>=1;s>>=1) { if (tid<s) red[tid]+=red[tid+s]; __syncthreads(); }
        r3 = red[0]; __syncthreads();
        red[tid] = am*uv; __syncthreads();
        for (int s=128;s>=1;s>>=1) { if (tid<s) red[tid]+=red[tid+s]; __syncthreads(); }
        r4 = red[0]; __syncthreads();
        red[tid] = (tid < NE) ? g_Q[e*NE+tid]*g_s[tid] : 0.f; __syncthreads();
        for (int s=128;s>=1;s>>=1) { if (tid<s) red[tid]+=red[tid+s]; __syncthreads(); }
        r5 = red[0]; __syncthreads();
        red[tid] = (tid < NE) ? g_CG[e*NE+tid]*g_Q[e*NE+tid] : 0.f; __syncthreads();
        for (int s=128;s>=1;s>>=1) { if (tid<s) red[tid]+=red[tid+s]; __syncthreads(); }
        r6 = red[0]; __syncthreads();

        if (tid == 0) {
            double se = (double)g_s[e];
            double bb = g_bbd;
            double bce = g_bcd[e];
            double d = 0.999, gam = (double)GAMv;
            double p_e = (double)r1 + 2.0*se*(double)r2 + bb*se*se;
            double quad_e = d*d*(double)r6
                          + 2.0*d*gam*((double)r3 + bce*(double)r5)
                          + gam*gam*((double)r4 + 2.0*(double)r2*(double)r5 + bb*se*(double)r5);
            atomicAdd(&g_accd[2], p_e);
            atomicAdd(&g_accd[3], quad_e);
        }
        if (e == 0) {
            red[tid] = 2.f*g_xsum[tid]*g_Wtb[tid]; __syncthreads();
            for (int s=128;s>=1;s>>=1) { if (tid<s) red[tid]+=red[tid+s]; __syncthreads(); }
            if (tid == 0) atomicAdd(&g_accd[0], (double)red[0] + (double)NN * g_bbd);
        }
        return;
    }
    // ---- Cnew = decay*Cents + gam*(A@W^T + s b^T) ----
    __shared__ float As[64][36];
    __shared__ float Ws[128][36];
    __shared__ float ss[64];
    int d0 = blockIdx.x * 128;
    if (tid < 64) ss[tid] = g_s[tid];
    float acc[4][2][4];
#pragma unroll
    for (int mt=0;mt<4;mt++)
#pragma unroll
        for (int nt=0;nt<2;nt++)
#pragma unroll
            for (int q=0;q<4;q++) acc[mt][nt][q]=0.f;

    for (int ch=0; ch<8; ch++) {
        int kc = ch*32;
#pragma unroll
        for (int l=0;l<2;l++) {
            int idx = tid + l*256;
            int row = idx>>3, q = (idx&7)*4;
            float4 v = *(const float4*)(g_A + (size_t)row*CC + kc + q);
            As[row][q]=v.x; As[row][q+1]=v.y; As[row][q+2]=v.z; As[row][q+3]=v.w;
        }
#pragma unroll
        for (int l=0;l<4;l++) {
            int idx = tid + l*256;
            int row = idx>>3, q = (idx&7)*4;
            float4 v = *(const float4*)(W + (size_t)(d0+row)*CC + kc + q);
            Ws[row][q]=v.x; Ws[row][q+1]=v.y; Ws[row][q+2]=v.z; Ws[row][q+3]=v.w;
        }
        __syncthreads();
#pragma unroll
        for (int k8=0;k8<4;k8++) {
            int kb = k8*8;
            uint32_t a[4][4], b[2][2];
#pragma unroll
            for (int mt=0;mt<4;mt++) {
                int e = mt*16 + gid;
                a[mt][0]=fb(As[e][kb+tig]);   a[mt][1]=fb(As[e+8][kb+tig]);
                a[mt][2]=fb(As[e][kb+tig+4]); a[mt][3]=fb(As[e+8][kb+tig+4]);
            }
#pragma unroll
            for (int nt=0;nt<2;nt++) {
                int dl = warp*16 + nt*8 + gid;
                b[nt][0]=fb(Ws[dl][kb+tig]); b[nt][1]=fb(Ws[dl][kb+tig+4]);
            }
#pragma unroll
            for (int mt=0;mt<4;mt++)
#pragma unroll
                for (int nt=0;nt<2;nt++) mma8(acc[mt][nt], a[mt], b[nt]);
        }
        __syncthreads();
    }
#pragma unroll
    for (int mt=0;mt<4;mt++)
#pragma unroll
        for (int nt=0;nt<2;nt++) {
            int e = mt*16 + gid;
            int d = d0 + warp*16 + nt*8 + 2*tig;
            float b0 = bvec[d], b1 = bvec[d+1];
            g_Cnew[(size_t)e*DD+d]       = DECAYv*cents[(size_t)e*DD+d]       + GAMv*(acc[mt][nt][0] + ss[e]*b0);
            g_Cnew[(size_t)e*DD+d+1]     = DECAYv*cents[(size_t)e*DD+d+1]     + GAMv*(acc[mt][nt][1] + ss[e]*b1);
            g_Cnew[(size_t)(e+8)*DD+d]   = DECAYv*cents[(size_t)(e+8)*DD+d]   + GAMv*(acc[mt][nt][2] + ss[e]*0.f + ss[e+8]*b0);
            g_Cnew[(size_t)(e+8)*DD+d+1] = DECAYv*cents[(size_t)(e+8)*DD+d+1] + GAMv*(acc[mt][nt][3] + ss[e+8]*b1);
        }
}

// ================= binned output GEMM (hi/lo), persistent 8 slots/expert =================
__global__ void __launch_bounds__(256) k_out(float* __restrict__ out) {
    __shared__ __align__(16) char smp[70400];
    int b = blockIdx.x;
    int tid=threadIdx.x, warp=tid>>5, lane=tid&31, gid=lane>>2, tig=lane&3;
    int e = b & 63;
    int cnt = g_cnt[e];
    float (*ys)[260] = (float (*)[260])smp;
    float (*Cw)[36]  = (float (*)[36])(smp + 33280);
    int* stok        = (int*)(smp + 33280 + 36864);
    int wm = warp>>2, wn = warp&3;

    for (int a0 = (b >> 6) * 32; a0 < cnt; a0 += 256) {
#pragma unroll
        for (int l=0;l<8;l++) {
            int idx = tid + l*256;
            int row = idx >> 6, q = idx & 63;
            int aa = a0 + row;
            float r = 0.f; int n = 0;
            float4 v = make_float4(0.f,0.f,0.f,0.f);
            if (aa < cnt) {
                n = g_tokn[e*NN+aa]; r = g_tokr[e*NN+aa];
                v = *(const float4*)(g_Y + (size_t)n*CC + q*4);
            }
            ys[row][q*4]=r*v.x; ys[row][q*4+1]=r*v.y; ys[row][q*4+2]=r*v.z; ys[row][q*4+3]=r*v.w;
            if (q == 0) stok[row] = n;
        }
        __syncthreads();
        float acc[8][4];
#pragma unroll
        for (int nt=0;nt<8;nt++)
#pragma unroll
            for (int q=0;q<4;q++) acc[nt][q]=0.f;

        for (int ch=0; ch<8; ch++) {
            int kc = ch*32;
#pragma unroll
            for (int l=0;l<8;l++) {
                int idx = tid + l*256;
                int row = idx >> 3, q = (idx & 7)*4;
                float4 v = *(const float4*)(g_Cnew + (size_t)e*DD + (size_t)row*CC + kc + q);
                Cw[row][q]=v.x; Cw[row][q+1]=v.y; Cw[row][q+2]=v.z; Cw[row][q+3]=v.w;
            }
            __syncthreads();
#pragma unroll
            for (int k8=0;k8<4;k8++) {
                int kb = k8*8;
                uint32_t ah[4], al[4];
                int m0 = wm*16 + gid;
                hilo(ys[m0][kc+kb+tig],     ah[0], al[0]);
                hilo(ys[m0+8][kc+kb+tig],   ah[1], al[1]);
                hilo(ys[m0][kc+kb+tig+4],   ah[2], al[2]);
                hilo(ys[m0+8][kc+kb+tig+4], ah[3], al[3]);
#pragma unroll
                for (int nt=0;nt<8;nt++) {
                    int nc = wn*64 + nt*8 + gid;
                    uint32_t bh[2], bl[2];
                    hilo(Cw[nc][kb+tig],   bh[0], bl[0]);
                    hilo(Cw[nc][kb+tig+4], bh[1], bl[1]);
                    mma8(acc[nt], ah, bh);
                    mma8(acc[nt], ah, bl);
                    mma8(acc[nt], al, bh);
                }
            }
            __syncthreads();
        }
        int t0 = wm*16 + gid;
        int r0 = stok[t0], r1 = stok[t0+8];
#pragma unroll
        for (int nt=0;nt<8;nt++) {
            int i = wn*64 + nt*8 + 2*tig;
            atomicAdd(out + (size_t)r0*ROUT + i,   acc[nt][0]);
            atomicAdd(out + (size_t)r0*ROUT + i+1, acc[nt][1]);
            atomicAdd(out + (size_t)r1*ROUT + i,   acc[nt][2]);
            atomicAdd(out + (size_t)r1*ROUT + i+1, acc[nt][3]);
        }
        __syncthreads();
    }
}

// ================= final: bias | loss scalar =================
__global__ void k_fin(float* __restrict__ out, const float* __restrict__ pwB, int out_size) {
    int b = blockIdx.x, tid = threadIdx.x;
    if (b < NN) {
        out[(size_t)b*ROUT + tid] += pwB[tid];
        return;
    }
    double S1 = 0.999*g_accd[1] + (double)GAMv*g_accd[2];
    double loss = 0.25*(g_accd[0] - 2.0*S1 + g_accd[3]) / ((double)NN * (double)DD);
    float lf = (float)loss;
    for (int i = NN*ROUT + tid; i < out_size; i += 256) out[i] = lf;
}

extern "C" void kernel_launch(void* const* d_in, const int* in_sizes, int n_in,
                              void* d_out, int out_size) {
    const float* x     = (const float*)d_in[0];
    const float* u     = (const float*)d_in[1];
    const float* W     = (const float*)d_in[2];
    const float* bvec  = (const float*)d_in[3];
    const float* pw1   = (const float*)d_in[4];
    const float* pwB   = (const float*)d_in[5];
    const float* cents = (const float*)d_in[6];
    float* out = (float*)d_out;

    k_zero<<<2048, 256>>>(out);
    k_p1<<<352, 256>>>(W, cents, bvec, x, pw1);
    k_big2<<<320, 256>>>(x, u);
    k_RX<<<64, 256>>>(x);
    k_cnew<<<576, 256>>>(W, cents, bvec);
    k_out<<<512, 256>>>(out);
    k_fin<<<NN + 1, 256>>>(out, pwB, out_size);
}

// round 11
// speedup vs baseline: 1.0817x; 1.0817x over previous
#include <cuda_runtime.h>
#include <cuda_bf16.h>
#include <math.h>
#include <stdint.h>

#define CC 256
#define NN 2048
#define DD 65536
#define NE 64
#define ROUT 256
#define DECAYv 0.999f
#define GAMv 4.8828125e-7f
#define COMMITv 0.25f

__device__ float g_M[CC*CC];
__device__ float g_G[NE*CC];
__device__ float g_A[NE*CC];
__device__ float g_Q[NE*NE];
__device__ float g_CG[NE*NE];
__device__ double g_cnormd[NE], g_bcd[NE], g_bbd;
__device__ float g_s[NE];
__device__ float g_Wtb[CC];
__device__ float g_xsum[CC];
__device__ double g_accd[4];      // 0:S0  1:S1a  2:p  3:quad
__device__ float g_Y[NN*CC];
__device__ float g_resp[NN*NE];
__device__ int   g_cnt[NE];
__device__ int   g_tokn[NE*NN];
__device__ float g_tokr[NE*NN];
__device__ float g_Cnew[NE*DD];

__device__ __forceinline__ void mma8(float* c, const uint32_t* a, const uint32_t* b) {
    asm volatile("mma.sync.aligned.m16n8k8.row.col.f32.tf32.tf32.f32 "
        "{%0,%1,%2,%3}, {%4,%5,%6,%7}, {%8,%9}, {%0,%1,%2,%3};"
        : "+f"(c[0]), "+f"(c[1]), "+f"(c[2]), "+f"(c[3])
        : "r"(a[0]), "r"(a[1]), "r"(a[2]), "r"(a[3]), "r"(b[0]), "r"(b[1]));
}
__device__ __forceinline__ void mma16bf(float* c, const uint32_t* a, const uint32_t* b) {
    asm volatile("mma.sync.aligned.m16n8k16.row.col.f32.bf16.bf16.f32 "
        "{%0,%1,%2,%3}, {%4,%5,%6,%7}, {%8,%9}, {%0,%1,%2,%3};"
        : "+f"(c[0]), "+f"(c[1]), "+f"(c[2]), "+f"(c[3])
        : "r"(a[0]), "r"(a[1]), "r"(a[2]), "r"(a[3]), "r"(b[0]), "r"(b[1]));
}
__device__ __forceinline__ uint32_t fb(float x) { return __float_as_uint(x); }
__device__ __forceinline__ void hilo(float v, uint32_t& h, uint32_t& l) {
    uint32_t hb = __float_as_uint(v) & 0xFFFFE000u;
    h = hb;
    l = fb(v - __uint_as_float(hb));
}

// ================= zero =================
__global__ void k_zero(float* __restrict__ out) {
    int i = blockIdx.x * 256 + threadIdx.x;
    if (i < NN*ROUT) out[i] = 0.f;
    if (i < CC*CC) g_M[i] = 0.f;
    if (i < NE*CC) { g_G[i]=0.f; g_A[i]=0.f; }
    if (i < NE*NE) { g_Q[i]=0.f; g_CG[i]=0.f; }
    if (i < CC) { g_Wtb[i] = 0.f; g_xsum[i] = 0.f; }
    if (i < NE) { g_cnormd[i]=0.0; g_bcd[i]=0.0; g_s[i]=0.f; g_cnt[i]=0; }
    if (i < 4) g_accd[i] = 0.0;
    if (i == 4) g_bbd = 0.0;
}

// ================= phase 1: gram(M bf16, 128) | centW (128) | Y (128) =================
__global__ void __launch_bounds__(256) k_p1(const float* __restrict__ W,
                                            const float* __restrict__ cents,
                                            const float* __restrict__ bvec,
                                            const float* __restrict__ x,
                                            const float* __restrict__ pw1) {
    __shared__ __align__(16) char smp[43008];
    int b = blockIdx.x;
    int tid=threadIdx.x, warp=tid>>5, lane=tid&31, gid=lane>>2, tig=lane&3;

    if (b < 128) {
        // ---- gram: M = W^T W in bf16 m16n8k16 (loss-only precision path) ----
        // Wp[kp][c] packs bf16(W[drow+2kp][c]), bf16(W[drow+2kp+1][c])
        uint32_t (*Wp)[260] = (uint32_t (*)[260])smp;
        int wm = warp>>2, wn = warp&3;
        int i0 = (b & 1) * 128;
        int d0 = (b >> 1) * 1024;
        float acc[4][8][4];
#pragma unroll
        for (int mt=0;mt<4;mt++)
#pragma unroll
            for (int nt=0;nt<8;nt++)
#pragma unroll
                for (int q=0;q<4;q++) acc[mt][nt][q]=0.f;

        for (int ch=0; ch<32; ch++) {
            int drow = d0 + ch*32;
#pragma unroll
            for (int l=0;l<16;l++) {
                int idx = tid + l*256;
                int kp = idx >> 8, c = idx & 255;
                float v0 = W[(size_t)(drow + 2*kp)   * CC + c];
                float v1 = W[(size_t)(drow + 2*kp+1) * CC + c];
                __nv_bfloat162 p2 = __floats2bfloat162_rn(v0, v1);
                Wp[kp][c] = *(uint32_t*)&p2;
            }
            __syncthreads();
#pragma unroll
            for (int st=0; st<2; st++) {
                int kpb = st*8;
                uint32_t a[4][4];
#pragma unroll
                for (int mt=0;mt<4;mt++) {
                    int ib = i0 + wm*64 + mt*16 + gid;
                    a[mt][0]=Wp[kpb+tig][ib];
                    a[mt][1]=Wp[kpb+tig][ib+8];
                    a[mt][2]=Wp[kpb+tig+4][ib];
                    a[mt][3]=Wp[kpb+tig+4][ib+8];
                }
#pragma unroll
                for (int nt=0;nt<8;nt++) {
                    int jb = wn*64 + nt*8 + gid;
                    uint32_t bv[2] = { Wp[kpb+tig][jb], Wp[kpb+tig+4][jb] };
#pragma unroll
                    for (int mt=0;mt<4;mt++) mma16bf(acc[mt][nt], a[mt], bv);
                }
            }
            __syncthreads();
        }
#pragma unroll
        for (int mt=0;mt<4;mt++)
#pragma unroll
            for (int nt=0;nt<8;nt++) {
                int i = i0 + wm*64 + mt*16 + gid;
                int j = wn*64 + nt*8 + 2*tig;
                atomicAdd(&g_M[i*CC+j],       acc[mt][nt][0]);
                atomicAdd(&g_M[i*CC+j+1],     acc[mt][nt][1]);
                atomicAdd(&g_M[(i+8)*CC+j],   acc[mt][nt][2]);
                atomicAdd(&g_M[(i+8)*CC+j+1], acc[mt][nt][3]);
            }
    } else if (b < 256) {
        // ---- centW: G = Cents@W (FULL hi/lo) + CG (hi/lo) + cnorm/bc/Wtb/bb ----
        float (*Cs)[36]  = (float (*)[36])smp;
        float (*Ws)[260] = (float (*)[260])(smp + 9216);
        float* bs        = (float*)(smp + 9216 + 33280);
        int blk = b - 128;
        int d0 = blk * 512;
        float accG[4][4][4], accCG[4][4];
#pragma unroll
        for (int mt=0;mt<4;mt++) {
#pragma unroll
            for (int nt=0;nt<4;nt++)
#pragma unroll
                for (int q=0;q<4;q++) accG[mt][nt][q]=0.f;
#pragma unroll
            for (int q=0;q<4;q++) accCG[mt][q]=0.f;
        }
        float accWtb=0.f, accCN=0.f, accBC=0.f, accBB=0.f;

        for (int ch=0; ch<16; ch++) {
            int dbase = d0 + ch*32;
#pragma unroll
            for (int l=0;l<2;l++) {
                int idx = tid + l*256;
                int e = idx>>3, q = (idx&7)*4;
                float4 v = *(const float4*)(cents + (size_t)e*DD + dbase + q);
                Cs[e][q]=v.x; Cs[e][q+1]=v.y; Cs[e][q+2]=v.z; Cs[e][q+3]=v.w;
            }
#pragma unroll
            for (int l=0;l<8;l++) {
                int idx = tid + l*256;
                int row = idx>>6, q = (idx&63)*4;
                float4 v = *(const float4*)(W + (size_t)(dbase+row)*CC + q);
                Ws[row][q]=v.x; Ws[row][q+1]=v.y; Ws[row][q+2]=v.z; Ws[row][q+3]=v.w;
            }
            if (tid < 32) bs[tid] = bvec[dbase + tid];
            __syncthreads();
            {
                float aw = 0.f;
                for (int k=0;k<32;k++) aw += bs[k]*Ws[k][tid];
                accWtb += aw;
            }
            if (tid < 64) {
                float cn=0.f, bc=0.f;
                for (int k=0;k<32;k++) { float c=Cs[tid][k]; cn+=c*c; bc+=c*bs[k]; }
                accCN += cn; accBC += bc;
            }
            if (tid == 64) {
                float sb=0.f;
                for (int k=0;k<32;k++) sb += bs[k]*bs[k];
                accBB += sb;
            }
#pragma unroll
            for (int k8=0;k8<4;k8++) {
                int kb = k8*8;
                uint32_t ah[4][4], al[4][4];
#pragma unroll
                for (int mt=0;mt<4;mt++) {
                    int e = mt*16 + gid;
                    hilo(Cs[e][kb+tig],     ah[mt][0], al[mt][0]);
                    hilo(Cs[e+8][kb+tig],   ah[mt][1], al[mt][1]);
                    hilo(Cs[e][kb+tig+4],   ah[mt][2], al[mt][2]);
                    hilo(Cs[e+8][kb+tig+4], ah[mt][3], al[mt][3]);
                }
#pragma unroll
                for (int nt=0;nt<4;nt++) {
                    int c = warp*32 + nt*8 + gid;
                    uint32_t bh[2], bl[2];
                    hilo(Ws[kb+tig][c],   bh[0], bl[0]);
                    hilo(Ws[kb+tig+4][c], bh[1], bl[1]);
#pragma unroll
                    for (int mt=0;mt<4;mt++) {
                        mma8(accG[mt][nt], ah[mt], bh);
                        mma8(accG[mt][nt], ah[mt], bl);
                        mma8(accG[mt][nt], al[mt], bh);
                    }
                }
                {
                    int n0q = warp*8 + gid;
                    uint32_t bh[2], bl[2];
                    hilo(Cs[n0q][kb+tig],   bh[0], bl[0]);
                    hilo(Cs[n0q][kb+tig+4], bh[1], bl[1]);
#pragma unroll
                    for (int mt=0;mt<4;mt++) {
                        mma8(accCG[mt], ah[mt], bh);
                        mma8(accCG[mt], ah[mt], bl);
                        mma8(accCG[mt], al[mt], bh);
                    }
                }
            }
            __syncthreads();
        }
#pragma unroll
        for (int mt=0;mt<4;mt++) {
#pragma unroll
            for (int nt=0;nt<4;nt++) {
                int e = mt*16 + gid;
                int c = warp*32 + nt*8 + 2*tig;
                atomicAdd(&g_G[e*CC+c],       accG[mt][nt][0]);
                atomicAdd(&g_G[e*CC+c+1],     accG[mt][nt][1]);
                atomicAdd(&g_G[(e+8)*CC+c],   accG[mt][nt][2]);
                atomicAdd(&g_G[(e+8)*CC+c+1], accG[mt][nt][3]);
            }
            int e = mt*16 + gid;
            int n = warp*8 + 2*tig;
            atomicAdd(&g_CG[e*NE+n],       accCG[mt][0]);
            atomicAdd(&g_CG[e*NE+n+1],     accCG[mt][1]);
            atomicAdd(&g_CG[(e+8)*NE+n],   accCG[mt][2]);
            atomicAdd(&g_CG[(e+8)*NE+n+1], accCG[mt][3]);
        }
        atomicAdd(&g_Wtb[tid], accWtb);
        if (tid < 64) { atomicAdd(&g_cnormd[tid], (double)accCN); atomicAdd(&g_bcd[tid], (double)accBC); }
        if (tid == 64) atomicAdd(&g_bbd, (double)accBB);
    } else {
        // ---- Y = X @ pw1^T  (hi/lo) ----
        float (*Xs)[36] = (float (*)[36])smp;
        float (*Bs)[36] = (float (*)[36])(smp + 9216);
        int yb = b - 256;
        int tok0 = (yb >> 2) * 64;
        int colgrp = yb & 3;
        const float* src = pw1 + (size_t)colgrp * 64 * CC;
        int wm = warp>>2, wn = warp&3;
        float acc[2][2][4];
#pragma unroll
        for (int mt=0;mt<2;mt++)
#pragma unroll
            for (int nt=0;nt<2;nt++)
#pragma unroll
                for (int q=0;q<4;q++) acc[mt][nt][q]=0.f;

        for (int ch=0; ch<8; ch++) {
            int kc = ch*32;
#pragma unroll
            for (int l=0;l<2;l++) {
                int idx = tid + l*256;
                int row = idx>>3, q = (idx&7)*4;
                float4 v = *(const float4*)(x + (size_t)(tok0+row)*CC + kc + q);
                Xs[row][q]=v.x; Xs[row][q+1]=v.y; Xs[row][q+2]=v.z; Xs[row][q+3]=v.w;
                float4 w = *(const float4*)(src + (size_t)row*CC + kc + q);
                Bs[row][q]=w.x; Bs[row][q+1]=w.y; Bs[row][q+2]=w.z; Bs[row][q+3]=w.w;
            }
            __syncthreads();
#pragma unroll
            for (int k8=0;k8<4;k8++) {
                int kb = k8*8;
                uint32_t ah[2][4], al[2][4], bh[2][2], bl[2][2];
#pragma unroll
                for (int mt=0;mt<2;mt++) {
                    int m0 = wm*32 + mt*16 + gid;
                    hilo(Xs[m0][kb+tig],     ah[mt][0], al[mt][0]);
                    hilo(Xs[m0+8][kb+tig],   ah[mt][1], al[mt][1]);
                    hilo(Xs[m0][kb+tig+4],   ah[mt][2], al[mt][2]);
                    hilo(Xs[m0+8][kb+tig+4], ah[mt][3], al[mt][3]);
                }
#pragma unroll
                for (int nt=0;nt<2;nt++) {
                    int nl = wn*16 + nt*8 + gid;
                    hilo(Bs[nl][kb+tig],   bh[nt][0], bl[nt][0]);
                    hilo(Bs[nl][kb+tig+4], bh[nt][1], bl[nt][1]);
                }
#pragma unroll
                for (int mt=0;mt<2;mt++)
#pragma unroll
                    for (int nt=0;nt<2;nt++) {
                        mma8(acc[mt][nt], ah[mt], bh[nt]);
                        mma8(acc[mt][nt], ah[mt], bl[nt]);
                        mma8(acc[mt][nt], al[mt], bh[nt]);
                    }
            }
            __syncthreads();
        }
#pragma unroll
        for (int mt=0;mt<2;mt++)
#pragma unroll
            for (int nt=0;nt<2;nt++) {
                int col = colgrp*64 + wn*16 + nt*8 + 2*tig;
#pragma unroll
                for (int rr=0;rr<2;rr++) {
                    int tok = tok0 + wm*32 + mt*16 + gid + rr*8;
                    g_Y[(size_t)tok*CC + col]   = acc[mt][nt][rr*2];
                    g_Y[(size_t)tok*CC + col+1] = acc[mt][nt][rr*2+1];
                }
            }
    }
}

// ================= phase 2 (64-token tiles): S0 from X@M | xG+softmax+binning =================
__global__ void __launch_bounds__(256) k_big2(const float* __restrict__ x,
                                              const float* __restrict__ u) {
    __shared__ __align__(16) char smp[36352];
    float (*Xs)[36] = (float (*)[36])smp;
    float (*Bs)[36] = (float (*)[36])(smp + 9216);
    float (*xgs)[68] = (float (*)[68])(smp + 18432);
    float* red = (float*)(smp + 18432);
    int b = blockIdx.x;
    int tid=threadIdx.x, warp=tid>>5, lane=tid&31, gid=lane>>2, tig=lane&3;
    int wm = warp>>2, wn = warp&3;
    int tok0, colgrp, mode;
    const float* src;
    if (b < 128) { tok0 = (b>>2)*64; colgrp = b&3; src = g_M + (size_t)colgrp*64*CC; mode=0; }
    else         { tok0 = (b-128)*64; colgrp = 0;  src = g_G; mode=1; }
    float acc[2][2][4];
#pragma unroll
    for (int mt=0;mt<2;mt++)
#pragma unroll
        for (int nt=0;nt<2;nt++)
#pragma unroll
            for (int q=0;q<4;q++) acc[mt][nt][q]=0.f;

    for (int ch=0; ch<8; ch++) {
        int kc = ch*32;
#pragma unroll
        for (int l=0;l<2;l++) {
            int idx = tid + l*256;
            int row = idx>>3, q = (idx&7)*4;
            float4 v = *(const float4*)(x + (size_t)(tok0+row)*CC + kc + q);
            Xs[row][q]=v.x; Xs[row][q+1]=v.y; Xs[row][q+2]=v.z; Xs[row][q+3]=v.w;
            float4 w = *(const float4*)(src + (size_t)row*CC + kc + q);
            Bs[row][q]=w.x; Bs[row][q+1]=w.y; Bs[row][q+2]=w.z; Bs[row][q+3]=w.w;
        }
        __syncthreads();
#pragma unroll
        for (int k8=0;k8<4;k8++) {
            int kb = k8*8;
            uint32_t ah[2][4], al[2][4], bh[2][2], bl[2][2];
#pragma unroll
            for (int mt=0;mt<2;mt++) {
                int m0 = wm*32 + mt*16 + gid;
                hilo(Xs[m0][kb+tig],     ah[mt][0], al[mt][0]);
                hilo(Xs[m0+8][kb+tig],   ah[mt][1], al[mt][1]);
                hilo(Xs[m0][kb+tig+4],   ah[mt][2], al[mt][2]);
                hilo(Xs[m0+8][kb+tig+4], ah[mt][3], al[mt][3]);
            }
#pragma unroll
            for (int nt=0;nt<2;nt++) {
                int nl = wn*16 + nt*8 + gid;
                hilo(Bs[nl][kb+tig],   bh[nt][0], bl[nt][0]);
                hilo(Bs[nl][kb+tig+4], bh[nt][1], bl[nt][1]);
            }
#pragma unroll
            for (int mt=0;mt<2;mt++)
#pragma unroll
                for (int nt=0;nt<2;nt++) {
                    mma8(acc[mt][nt], ah[mt], bh[nt]);
                    mma8(acc[mt][nt], ah[mt], bl[nt]);
                    mma8(acc[mt][nt], al[mt], bh[nt]);
                }
        }
        __syncthreads();
    }
    if (mode == 0) {
        float s0 = 0.f;
#pragma unroll
        for (int mt=0;mt<2;mt++)
#pragma unroll
            for (int nt=0;nt<2;nt++) {
                int col = colgrp*64 + wn*16 + nt*8 + 2*tig;
#pragma unroll
                for (int rr=0;rr<2;rr++) {
                    int tok = tok0 + wm*32 + mt*16 + gid + rr*8;
                    s0 += acc[mt][nt][rr*2]   * x[(size_t)tok*CC + col];
                    s0 += acc[mt][nt][rr*2+1] * x[(size_t)tok*CC + col+1];
                }
            }
        red[tid] = s0; __syncthreads();
        for (int s=128;s>=1;s>>=1) { if (tid<s) red[tid]+=red[tid+s]; __syncthreads(); }
        if (tid == 0) atomicAdd(&g_accd[0], (double)red[0]);
        return;
    }
#pragma unroll
    for (int mt=0;mt<2;mt++)
#pragma unroll
        for (int nt=0;nt<2;nt++) {
            int col = wn*16 + nt*8 + 2*tig;
#pragma unroll
            for (int rr=0;rr<2;rr++) {
                int lt = wm*32 + mt*16 + gid + rr*8;
                xgs[lt][col]   = acc[mt][nt][rr*2];
                xgs[lt][col+1] = acc[mt][nt][rr*2+1];
            }
        }
    __syncthreads();
    float cn0 = (float)g_cnormd[lane], cn1 = (float)g_cnormd[lane+32];
    float bc0 = (float)g_bcd[lane],    bc1 = (float)g_bcd[lane+32];
    float s1acc = 0.f;
    for (int k=0;k<8;k++) {
        int lt = warp*8 + k;
        size_t n = tok0 + lt;
        float xg0 = xgs[lt][lane]    + bc0;
        float xg1 = xgs[lt][lane+32] + bc1;
        float l0 = 2.f*xg0 - cn0 - logf(-logf(u[n*NE+lane]));
        float l1 = 2.f*xg1 - cn1 - logf(-logf(u[n*NE+lane+32]));
        float m = fmaxf(l0, l1);
#pragma unroll
        for (int o=16;o>=1;o>>=1) m = fmaxf(m, __shfl_xor_sync(0xffffffffu, m, o));
        float ex0 = expf(l0 - m), ex1 = expf(l1 - m);
        float S = ex0 + ex1;
#pragma unroll
        for (int o=16;o>=1;o>>=1) S += __shfl_xor_sync(0xffffffffu, S, o);
        float r0 = ex0 / S, r1 = ex1 / S;
        g_resp[n*NE+lane]    = r0;
        g_resp[n*NE+lane+32] = r1;
        float s1 = r0*xg0 + r1*xg1;
#pragma unroll
        for (int o=16;o>=1;o>>=1) s1 += __shfl_xor_sync(0xffffffffu, s1, o);
        if (lane == 0) s1acc += s1;
        if (r0 > 1e-9f) {
            int p = atomicAdd(&g_cnt[lane], 1);
            g_tokn[lane*NN+p] = (int)n; g_tokr[lane*NN+p] = r0;
        }
        if (r1 > 1e-9f) {
            int p = atomicAdd(&g_cnt[lane+32], 1);
            g_tokn[(lane+32)*NN+p] = (int)n; g_tokr[(lane+32)*NN+p] = r1;
        }
    }
    if (lane == 0) atomicAdd(&g_accd[1], (double)s1acc);
}

// ================= A=R^T X (plain), Q=R^T R (hi/lo), s, xsum  (32 tokens/blk) =================
__global__ void __launch_bounds__(256) k_RX(const float* __restrict__ x) {
    __shared__ float Rs[32][68];
    __shared__ float Xs[32][260];
    int tid=threadIdx.x, warp=tid>>5, lane=tid&31, gid=lane>>2, tig=lane&3;
    int nb = blockIdx.x * 32;
    float accA[4][4][4], accQ[4][4];
#pragma unroll
    for (int mt=0;mt<4;mt++) {
#pragma unroll
        for (int nt=0;nt<4;nt++)
#pragma unroll
            for (int q=0;q<4;q++) accA[mt][nt][q]=0.f;
#pragma unroll
        for (int q=0;q<4;q++) accQ[mt][q]=0.f;
    }
    float sp=0.f, xsacc=0.f;

#pragma unroll
    for (int l=0;l<8;l++) {
        int idx = tid + l*256;
        int row = idx>>6, e2 = idx&63;
        Rs[row][e2] = g_resp[(size_t)(nb+row)*NE + e2];
    }
#pragma unroll
    for (int l=0;l<8;l++) {
        int idx = tid + l*256;
        int row = idx>>6, q = (idx&63)*4;
        float4 v = *(const float4*)(x + (size_t)(nb+row)*CC + q);
        Xs[row][q]=v.x; Xs[row][q+1]=v.y; Xs[row][q+2]=v.z; Xs[row][q+3]=v.w;
    }
    __syncthreads();
    if (tid < 64) {
        for (int k=0;k<32;k++) sp += Rs[k][tid];
    }
    for (int k=0;k<32;k++) xsacc += Xs[k][tid];
#pragma unroll
    for (int k8=0;k8<4;k8++) {
        int kb = k8*8;
        uint32_t am[4][4], amh[4][4], aml[4][4];
#pragma unroll
        for (int mt=0;mt<4;mt++) {
            int m0 = mt*16;
            float v0 = Rs[kb+tig][m0+gid],   v1 = Rs[kb+tig][m0+gid+8];
            float v2 = Rs[kb+tig+4][m0+gid], v3 = Rs[kb+tig+4][m0+gid+8];
            am[mt][0]=fb(v0); am[mt][1]=fb(v1); am[mt][2]=fb(v2); am[mt][3]=fb(v3);
            hilo(v0, amh[mt][0], aml[mt][0]); hilo(v1, amh[mt][1], aml[mt][1]);
            hilo(v2, amh[mt][2], aml[mt][2]); hilo(v3, amh[mt][3], aml[mt][3]);
        }
#pragma unroll
        for (int nt=0;nt<4;nt++) {
            int c = warp*32 + nt*8 + gid;
            uint32_t bx[2] = { fb(Xs[kb+tig][c]), fb(Xs[kb+tig+4][c]) };
#pragma unroll
            for (int mt=0;mt<4;mt++) mma8(accA[mt][nt], am[mt], bx);
        }
        {
            int eq = warp*8 + gid;
            uint32_t bqh[2], bql[2];
            hilo(Rs[kb+tig][eq],   bqh[0], bql[0]);
            hilo(Rs[kb+tig+4][eq], bqh[1], bql[1]);
#pragma unroll
            for (int mt=0;mt<4;mt++) {
                mma8(accQ[mt], amh[mt], bqh);
                mma8(accQ[mt], amh[mt], bql);
                mma8(accQ[mt], aml[mt], bqh);
            }
        }
    }
#pragma unroll
    for (int mt=0;mt<4;mt++) {
#pragma unroll
        for (int nt=0;nt<4;nt++) {
            int e = mt*16 + gid;
            int c = warp*32 + nt*8 + 2*tig;
            atomicAdd(&g_A[e*CC+c],        accA[mt][nt][0]);
            atomicAdd(&g_A[e*CC+c+1],      accA[mt][nt][1]);
            atomicAdd(&g_A[(e+8)*CC+c],    accA[mt][nt][2]);
            atomicAdd(&g_A[(e+8)*CC+c+1],  accA[mt][nt][3]);
        }
        int e = mt*16 + gid;
        int eq = warp*8 + 2*tig;
        atomicAdd(&g_Q[e*NE+eq],       accQ[mt][0]);
        atomicAdd(&g_Q[e*NE+eq+1],     accQ[mt][1]);
        atomicAdd(&g_Q[(e+8)*NE+eq],   accQ[mt][2]);
        atomicAdd(&g_Q[(e+8)*NE+eq+1], accQ[mt][3]);
    }
    if (tid < 64) atomicAdd(&g_s[tid], sp);
    atomicAdd(&g_xsum[tid], xsacc);
}

// ================= Cnew (512 blks) | loss contractions (64 blks) =================
__global__ void __launch_bounds__(256) k_cnew(const float* __restrict__ W,
                                              const float* __restrict__ cents,
                                              const float* __restrict__ bvec) {
    int tid=threadIdx.x, warp=tid>>5, lane=tid&31, gid=lane>>2, tig=lane&3;
    if (blockIdx.x >= 512) {
        int e = blockIdx.x - 512;
        __shared__ float As[256];
        __shared__ float red[256];
        As[tid] = g_A[e*CC + tid];
        __syncthreads();
        float uv = 0.f;
        for (int e2=0;e2<NE;e2++) uv += g_Q[e*NE+e2] * g_A[e2*CC + tid];
        float am = 0.f;
        for (int c=0;c<CC;c++) am += As[c] * g_M[c*CC + tid];
        float a = As[tid];
        float ge = g_G[e*CC + tid];
        float wtb = g_Wtb[tid];

        float r1, r2, r3, r4, r5, r6;
        red[tid] = am*a; __syncthreads();
        for (int s=128;s>=1;s>>=1) { if (tid<s) red[tid]+=red[tid+s]; __syncthreads(); }
        r1 = red[0]; __syncthreads();
        red[tid] = a*wtb; __syncthreads();
        for (int s=128;s>=1;s>>=1) { if (tid<s) red[tid]+=red[tid+s]; __syncthreads(); }
        r2 = red[0]; __syncthreads();
        red[tid] = ge*uv; __syncthreads();
        for (int s=128;s>=1;s>>=1) { if (tid<s) red[tid]+=red[tid+s]; __syncthreads(); }
        r3 = red[0]; __syncthreads();
        red[tid] = am*uv; __syncthreads();
        for (int s=128;s>=1;s>>=1) { if (tid<s) red[tid]+=red[tid+s]; __syncthreads(); }
        r4 = red[0]; __syncthreads();
        red[tid] = (tid < NE) ? g_Q[e*NE+tid]*g_s[tid] : 0.f; __syncthreads();
        for (int s=128;s>=1;s>>=1) { if (tid<s) red[tid]+=red[tid+s]; __syncthreads(); }
        r5 = red[0]; __syncthreads();
        red[tid] = (tid < NE) ? g_CG[e*NE+tid]*g_Q[e*NE+tid] : 0.f; __syncthreads();
        for (int s=128;s>=1;s>>=1) { if (tid<s) red[tid]+=red[tid+s]; __syncthreads(); }
        r6 = red[0]; __syncthreads();

        if (tid == 0) {
            double se = (double)g_s[e];
            double bb = g_bbd;
            double bce = g_bcd[e];
            double d = 0.999, gam = (double)GAMv;
            double p_e = (double)r1 + 2.0*se*(double)r2 + bb*se*se;
            double quad_e = d*d*(double)r6
                          + 2.0*d*gam*((double)r3 + bce*(double)r5)
                          + gam*gam*((double)r4 + 2.0*(double)r2*(double)r5 + bb*se*(double)r5);
            atomicAdd(&g_accd[2], p_e);
            atomicAdd(&g_accd[3], quad_e);
        }
        if (e == 0) {
            red[tid] = 2.f*g_xsum[tid]*g_Wtb[tid]; __syncthreads();
            for (int s=128;s>=1;s>>=1) { if (tid<s) red[tid]+=red[tid+s]; __syncthreads(); }
            if (tid == 0) atomicAdd(&g_accd[0], (double)red[0] + (double)NN * g_bbd);
        }
        return;
    }
    __shared__ float As[64][36];
    __shared__ float Ws[128][36];
    __shared__ float ss[64];
    int d0 = blockIdx.x * 128;
    if (tid < 64) ss[tid] = g_s[tid];
    float acc[4][2][4];
#pragma unroll
    for (int mt=0;mt<4;mt++)
#pragma unroll
        for (int nt=0;nt<2;nt++)
#pragma unroll
            for (int q=0;q<4;q++) acc[mt][nt][q]=0.f;

    for (int ch=0; ch<8; ch++) {
        int kc = ch*32;
#pragma unroll
        for (int l=0;l<2;l++) {
            int idx = tid + l*256;
            int row = idx>>3, q = (idx&7)*4;
            float4 v = *(const float4*)(g_A + (size_t)row*CC + kc + q);
            As[row][q]=v.x; As[row][q+1]=v.y; As[row][q+2]=v.z; As[row][q+3]=v.w;
        }
#pragma unroll
        for (int l=0;l<4;l++) {
            int idx = tid + l*256;
            int row = idx>>3, q = (idx&7)*4;
            float4 v = *(const float4*)(W + (size_t)(d0+row)*CC + kc + q);
            Ws[row][q]=v.x; Ws[row][q+1]=v.y; Ws[row][q+2]=v.z; Ws[row][q+3]=v.w;
        }
        __syncthreads();
#pragma unroll
        for (int k8=0;k8<4;k8++) {
            int kb = k8*8;
            uint32_t a[4][4], b[2][2];
#pragma unroll
            for (int mt=0;mt<4;mt++) {
                int e = mt*16 + gid;
                a[mt][0]=fb(As[e][kb+tig]);   a[mt][1]=fb(As[e+8][kb+tig]);
                a[mt][2]=fb(As[e][kb+tig+4]); a[mt][3]=fb(As[e+8][kb+tig+4]);
            }
#pragma unroll
            for (int nt=0;nt<2;nt++) {
                int dl = warp*16 + nt*8 + gid;
                b[nt][0]=fb(Ws[dl][kb+tig]); b[nt][1]=fb(Ws[dl][kb+tig+4]);
            }
#pragma unroll
            for (int mt=0;mt<4;mt++)
#pragma unroll
                for (int nt=0;nt<2;nt++) mma8(acc[mt][nt], a[mt], b[nt]);
        }
        __syncthreads();
    }
#pragma unroll
    for (int mt=0;mt<4;mt++)
#pragma unroll
        for (int nt=0;nt<2;nt++) {
            int e = mt*16 + gid;
            int d = d0 + warp*16 + nt*8 + 2*tig;
            float b0 = bvec[d], b1 = bvec[d+1];
            g_Cnew[(size_t)e*DD+d]       = DECAYv*cents[(size_t)e*DD+d]       + GAMv*(acc[mt][nt][0] + ss[e]*b0);
            g_Cnew[(size_t)e*DD+d+1]     = DECAYv*cents[(size_t)e*DD+d+1]     + GAMv*(acc[mt][nt][1] + ss[e]*b1);
            g_Cnew[(size_t)(e+8)*DD+d]   = DECAYv*cents[(size_t)(e+8)*DD+d]   + GAMv*(acc[mt][nt][2] + ss[e+8]*b0);
            g_Cnew[(size_t)(e+8)*DD+d+1] = DECAYv*cents[(size_t)(e+8)*DD+d+1] + GAMv*(acc[mt][nt][3] + ss[e+8]*b1);
        }
}

// ================= binned output GEMM (hi/lo), persistent 8 slots/expert =================
__global__ void __launch_bounds__(256) k_out(float* __restrict__ out) {
    __shared__ __align__(16) char smp[70400];
    int b = blockIdx.x;
    int tid=threadIdx.x, warp=tid>>5, lane=tid&31, gid=lane>>2, tig=lane&3;
    int e = b & 63;
    int cnt = g_cnt[e];
    float (*ys)[260] = (float (*)[260])smp;
    float (*Cw)[36]  = (float (*)[36])(smp + 33280);
    int* stok        = (int*)(smp + 33280 + 36864);
    int wm = warp>>2, wn = warp&3;

    for (int a0 = (b >> 6) * 32; a0 < cnt; a0 += 256) {
#pragma unroll
        for (int l=0;l<8;l++) {
            int idx = tid + l*256;
            int row = idx >> 6, q = idx & 63;
            int aa = a0 + row;
            float r = 0.f; int n = 0;
            float4 v = make_float4(0.f,0.f,0.f,0.f);
            if (aa < cnt) {
                n = g_tokn[e*NN+aa]; r = g_tokr[e*NN+aa];
                v = *(const float4*)(g_Y + (size_t)n*CC + q*4);
            }
            ys[row][q*4]=r*v.x; ys[row][q*4+1]=r*v.y; ys[row][q*4+2]=r*v.z; ys[row][q*4+3]=r*v.w;
            if (q == 0) stok[row] = n;
        }
        __syncthreads();
        float acc[8][4];
#pragma unroll
        for (int nt=0;nt<8;nt++)
#pragma unroll
            for (int q=0;q<4;q++) acc[nt][q]=0.f;

        for (int ch=0; ch<8; ch++) {
            int kc = ch*32;
#pragma unroll
            for (int l=0;l<8;l++) {
                int idx = tid + l*256;
                int row = idx >> 3, q = (idx & 7)*4;
                float4 v = *(const float4*)(g_Cnew + (size_t)e*DD + (size_t)row*CC + kc + q);
                Cw[row][q]=v.x; Cw[row][q+1]=v.y; Cw[row][q+2]=v.z; Cw[row][q+3]=v.w;
            }
            __syncthreads();
#pragma unroll
            for (int k8=0;k8<4;k8++) {
                int kb = k8*8;
                uint32_t ah[4], al[4];
                int m0 = wm*16 + gid;
                hilo(ys[m0][kc+kb+tig],     ah[0], al[0]);
                hilo(ys[m0+8][kc+kb+tig],   ah[1], al[1]);
                hilo(ys[m0][kc+kb+tig+4],   ah[2], al[2]);
                hilo(ys[m0+8][kc+kb+tig+4], ah[3], al[3]);
#pragma unroll
                for (int nt=0;nt<8;nt++) {
                    int nc = wn*64 + nt*8 + gid;
                    uint32_t bh[2], bl[2];
                    hilo(Cw[nc][kb+tig],   bh[0], bl[0]);
                    hilo(Cw[nc][kb+tig+4], bh[1], bl[1]);
                    mma8(acc[nt], ah, bh);
                    mma8(acc[nt], ah, bl);
                    mma8(acc[nt], al, bh);
                }
            }
            __syncthreads();
        }
        int t0 = wm*16 + gid;
        int r0 = stok[t0], r1 = stok[t0+8];
#pragma unroll
        for (int nt=0;nt<8;nt++) {
            int i = wn*64 + nt*8 + 2*tig;
            atomicAdd(out + (size_t)r0*ROUT + i,   acc[nt][0]);
            atomicAdd(out + (size_t)r0*ROUT + i+1, acc[nt][1]);
            atomicAdd(out + (size_t)r1*ROUT + i,   acc[nt][2]);
            atomicAdd(out + (size_t)r1*ROUT + i+1, acc[nt][3]);
        }
        __syncthreads();
    }
}

// ================= final: bias | loss scalar =================
__global__ void k_fin(float* __restrict__ out, const float* __restrict__ pwB, int out_size) {
    int b = blockIdx.x, tid = threadIdx.x;
    if (b < NN) {
        out[(size_t)b*ROUT + tid] += pwB[tid];
        return;
    }
    double S1 = 0.999*g_accd[1] + (double)GAMv*g_accd[2];
    double loss = 0.25*(g_accd[0] - 2.0*S1 + g_accd[3]) / ((double)NN * (double)DD);
    float lf = (float)loss;
    for (int i = NN*ROUT + tid; i < out_size; i += 256) out[i] = lf;
}

extern "C" void kernel_launch(void* const* d_in, const int* in_sizes, int n_in,
                              void* d_out, int out_size) {
    const float* x     = (const float*)d_in[0];
    const float* u     = (const float*)d_in[1];
    const float* W     = (const float*)d_in[2];
    const float* bvec  = (const float*)d_in[3];
    const float* pw1   = (const float*)d_in[4];
    const float* pwB   = (const float*)d_in[5];
    const float* cents = (const float*)d_in[6];
    float* out = (float*)d_out;

    k_zero<<<2048, 256>>>(out);
    k_p1<<<384, 256>>>(W, cents, bvec, x, pw1);
    k_big2<<<160, 256>>>(x, u);
    k_RX<<<64, 256>>>(x);
    k_cnew<<<576, 256>>>(W, cents, bvec);
    k_out<<<512, 256>>>(out);
    k_fin<<<NN + 1, 256>>>(out, pwB, out_size);
}

// round 12
// speedup vs baseline: 1.0994x; 1.0164x over previous
#include <cuda_runtime.h>
#include <cuda_bf16.h>
#include <math.h>
#include <stdint.h>

#define CC 256
#define NN 2048
#define DD 65536
#define NE 64
#define ROUT 256
#define DECAYv 0.999f
#define GAMv 4.8828125e-7f
#define COMMITv 0.25f

__device__ float g_M[CC*CC];
__device__ float g_G[NE*CC];
__device__ float g_A[NE*CC];
__device__ float g_Q[NE*NE];
__device__ float g_CG[NE*NE];
__device__ double g_cnormd[NE], g_bcd[NE], g_bbd;
__device__ float g_s[NE];
__device__ float g_Wtb[CC];
__device__ float g_xsum[CC];
__device__ double g_accd[4];      // 0:S0  1:S1a  2:p  3:quad
__device__ float g_Y[NN*CC];
__device__ float g_resp[NN*NE];
__device__ int   g_cnt[NE];
__device__ int   g_tokn[NE*NN];
__device__ float g_tokr[NE*NN];
__device__ float g_Cnew[NE*DD];

__device__ __forceinline__ void mma8(float* c, const uint32_t* a, const uint32_t* b) {
    asm volatile("mma.sync.aligned.m16n8k8.row.col.f32.tf32.tf32.f32 "
        "{%0,%1,%2,%3}, {%4,%5,%6,%7}, {%8,%9}, {%0,%1,%2,%3};"
        : "+f"(c[0]), "+f"(c[1]), "+f"(c[2]), "+f"(c[3])
        : "r"(a[0]), "r"(a[1]), "r"(a[2]), "r"(a[3]), "r"(b[0]), "r"(b[1]));
}
__device__ __forceinline__ void mma16bf(float* c, const uint32_t* a, const uint32_t* b) {
    asm volatile("mma.sync.aligned.m16n8k16.row.col.f32.bf16.bf16.f32 "
        "{%0,%1,%2,%3}, {%4,%5,%6,%7}, {%8,%9}, {%0,%1,%2,%3};"
        : "+f"(c[0]), "+f"(c[1]), "+f"(c[2]), "+f"(c[3])
        : "r"(a[0]), "r"(a[1]), "r"(a[2]), "r"(a[3]), "r"(b[0]), "r"(b[1]));
}
__device__ __forceinline__ uint32_t fb(float x) { return __float_as_uint(x); }
__device__ __forceinline__ uint32_t pk2(float a, float b) {
    __nv_bfloat162 p = __floats2bfloat162_rn(a, b);
    return *(uint32_t*)&p;
}
__device__ __forceinline__ void hilo(float v, uint32_t& h, uint32_t& l) {
    uint32_t hb = __float_as_uint(v) & 0xFFFFE000u;
    h = hb;
    l = fb(v - __uint_as_float(hb));
}

// ================= zero =================
__global__ void k_zero(float* __restrict__ out) {
    int i = blockIdx.x * 256 + threadIdx.x;
    if (i < NN*ROUT) out[i] = 0.f;
    if (i < CC*CC) g_M[i] = 0.f;
    if (i < NE*CC) { g_G[i]=0.f; g_A[i]=0.f; }
    if (i < NE*NE) { g_Q[i]=0.f; g_CG[i]=0.f; }
    if (i < CC) { g_Wtb[i] = 0.f; g_xsum[i] = 0.f; }
    if (i < NE) { g_cnormd[i]=0.0; g_bcd[i]=0.0; g_s[i]=0.f; g_cnt[i]=0; }
    if (i < 4) g_accd[i] = 0.0;
    if (i == 4) g_bbd = 0.0;
}

// ================= phase 1: gram(M bf16,128) | centW(G hi/lo + CG bf16, 256) | Y(128) =================
__global__ void __launch_bounds__(256) k_p1(const float* __restrict__ W,
                                            const float* __restrict__ cents,
                                            const float* __restrict__ bvec,
                                            const float* __restrict__ x,
                                            const float* __restrict__ pw1) {
    __shared__ __align__(16) char smp[47104];
    int b = blockIdx.x;
    int tid=threadIdx.x, warp=tid>>5, lane=tid&31, gid=lane>>2, tig=lane&3;

    if (b < 128) {
        // ---- gram: M = W^T W in bf16 m16n8k16 (loss-only path) ----
        uint32_t (*Wp)[260] = (uint32_t (*)[260])smp;
        int wm = warp>>2, wn = warp&3;
        int i0 = (b & 1) * 128;
        int d0 = (b >> 1) * 1024;
        float acc[4][8][4];
#pragma unroll
        for (int mt=0;mt<4;mt++)
#pragma unroll
            for (int nt=0;nt<8;nt++)
#pragma unroll
                for (int q=0;q<4;q++) acc[mt][nt][q]=0.f;

        for (int ch=0; ch<32; ch++) {
            int drow = d0 + ch*32;
#pragma unroll
            for (int l=0;l<16;l++) {
                int idx = tid + l*256;
                int kp = idx >> 8, c = idx & 255;
                float v0 = W[(size_t)(drow + 2*kp)   * CC + c];
                float v1 = W[(size_t)(drow + 2*kp+1) * CC + c];
                Wp[kp][c] = pk2(v0, v1);
            }
            __syncthreads();
#pragma unroll
            for (int st=0; st<2; st++) {
                int kpb = st*8;
                uint32_t a[4][4];
#pragma unroll
                for (int mt=0;mt<4;mt++) {
                    int ib = i0 + wm*64 + mt*16 + gid;
                    a[mt][0]=Wp[kpb+tig][ib];
                    a[mt][1]=Wp[kpb+tig][ib+8];
                    a[mt][2]=Wp[kpb+tig+4][ib];
                    a[mt][3]=Wp[kpb+tig+4][ib+8];
                }
#pragma unroll
                for (int nt=0;nt<8;nt++) {
                    int jb = wn*64 + nt*8 + gid;
                    uint32_t bv[2] = { Wp[kpb+tig][jb], Wp[kpb+tig+4][jb] };
#pragma unroll
                    for (int mt=0;mt<4;mt++) mma16bf(acc[mt][nt], a[mt], bv);
                }
            }
            __syncthreads();
        }
#pragma unroll
        for (int mt=0;mt<4;mt++)
#pragma unroll
            for (int nt=0;nt<8;nt++) {
                int i = i0 + wm*64 + mt*16 + gid;
                int j = wn*64 + nt*8 + 2*tig;
                atomicAdd(&g_M[i*CC+j],       acc[mt][nt][0]);
                atomicAdd(&g_M[i*CC+j+1],     acc[mt][nt][1]);
                atomicAdd(&g_M[(i+8)*CC+j],   acc[mt][nt][2]);
                atomicAdd(&g_M[(i+8)*CC+j+1], acc[mt][nt][3]);
            }
    } else if (b < 384) {
        // ---- centW: G hi/lo (routing) + CG bf16 (loss) + cnorm/bc/Wtb/bb ----
        float (*Cs)[36]  = (float (*)[36])smp;                       // 9216
        float (*Ws)[260] = (float (*)[260])(smp + 9216);             // 33280
        uint32_t (*Cpk)[68] = (uint32_t (*)[68])(smp + 42496);       // 16x68x4 = 4352
        float* bs        = (float*)(smp + 46848);                    // 128
        int blk = b - 128;
        int d0 = blk * 256;
        float accG[4][4][4], accCG[4][4];
#pragma unroll
        for (int mt=0;mt<4;mt++) {
#pragma unroll
            for (int nt=0;nt<4;nt++)
#pragma unroll
                for (int q=0;q<4;q++) accG[mt][nt][q]=0.f;
#pragma unroll
            for (int q=0;q<4;q++) accCG[mt][q]=0.f;
        }
        float accWtb=0.f, accCN=0.f, accBC=0.f, accBB=0.f;

        for (int ch=0; ch<8; ch++) {
            int dbase = d0 + ch*32;
#pragma unroll
            for (int l=0;l<2;l++) {
                int idx = tid + l*256;
                int e = idx>>3, q = (idx&7)*4;
                float4 v = *(const float4*)(cents + (size_t)e*DD + dbase + q);
                Cs[e][q]=v.x; Cs[e][q+1]=v.y; Cs[e][q+2]=v.z; Cs[e][q+3]=v.w;
                Cpk[q>>1][e]     = pk2(v.x, v.y);
                Cpk[(q>>1)+1][e] = pk2(v.z, v.w);
            }
#pragma unroll
            for (int l=0;l<8;l++) {
                int idx = tid + l*256;
                int row = idx>>6, q = (idx&63)*4;
                float4 v = *(const float4*)(W + (size_t)(dbase+row)*CC + q);
                Ws[row][q]=v.x; Ws[row][q+1]=v.y; Ws[row][q+2]=v.z; Ws[row][q+3]=v.w;
            }
            if (tid < 32) bs[tid] = bvec[dbase + tid];
            __syncthreads();
            {
                float aw = 0.f;
                for (int k=0;k<32;k++) aw += bs[k]*Ws[k][tid];
                accWtb += aw;
            }
            if (tid < 64) {
                float cn=0.f, bc=0.f;
                for (int k=0;k<32;k++) { float c=Cs[tid][k]; cn+=c*c; bc+=c*bs[k]; }
                accCN += cn; accBC += bc;
            }
            if (tid == 64) {
                float sb=0.f;
                for (int k=0;k<32;k++) sb += bs[k]*bs[k];
                accBB += sb;
            }
            // G: full hi/lo tf32 (routing-critical)
#pragma unroll
            for (int k8=0;k8<4;k8++) {
                int kb = k8*8;
                uint32_t ah[4][4], al[4][4];
#pragma unroll
                for (int mt=0;mt<4;mt++) {
                    int e = mt*16 + gid;
                    hilo(Cs[e][kb+tig],     ah[mt][0], al[mt][0]);
                    hilo(Cs[e+8][kb+tig],   ah[mt][1], al[mt][1]);
                    hilo(Cs[e][kb+tig+4],   ah[mt][2], al[mt][2]);
                    hilo(Cs[e+8][kb+tig+4], ah[mt][3], al[mt][3]);
                }
#pragma unroll
                for (int nt=0;nt<4;nt++) {
                    int c = warp*32 + nt*8 + gid;
                    uint32_t bh[2], bl[2];
                    hilo(Ws[kb+tig][c],   bh[0], bl[0]);
                    hilo(Ws[kb+tig+4][c], bh[1], bl[1]);
#pragma unroll
                    for (int mt=0;mt<4;mt++) {
                        mma8(accG[mt][nt], ah[mt], bh);
                        mma8(accG[mt][nt], ah[mt], bl);
                        mma8(accG[mt][nt], al[mt], bh);
                    }
                }
            }
            // CG: bf16 m16n8k16 (loss-only)
#pragma unroll
            for (int kpb=0; kpb<16; kpb+=8) {
                uint32_t a[4][4], bcg[2];
#pragma unroll
                for (int mt=0;mt<4;mt++) {
                    int e = mt*16 + gid;
                    a[mt][0]=Cpk[kpb+tig][e];
                    a[mt][1]=Cpk[kpb+tig][e+8];
                    a[mt][2]=Cpk[kpb+tig+4][e];
                    a[mt][3]=Cpk[kpb+tig+4][e+8];
                }
                int n0q = warp*8 + gid;
                bcg[0]=Cpk[kpb+tig][n0q];
                bcg[1]=Cpk[kpb+tig+4][n0q];
#pragma unroll
                for (int mt=0;mt<4;mt++) mma16bf(accCG[mt], a[mt], bcg);
            }
            __syncthreads();
        }
#pragma unroll
        for (int mt=0;mt<4;mt++) {
#pragma unroll
            for (int nt=0;nt<4;nt++) {
                int e = mt*16 + gid;
                int c = warp*32 + nt*8 + 2*tig;
                atomicAdd(&g_G[e*CC+c],       accG[mt][nt][0]);
                atomicAdd(&g_G[e*CC+c+1],     accG[mt][nt][1]);
                atomicAdd(&g_G[(e+8)*CC+c],   accG[mt][nt][2]);
                atomicAdd(&g_G[(e+8)*CC+c+1], accG[mt][nt][3]);
            }
            int e = mt*16 + gid;
            int n = warp*8 + 2*tig;
            atomicAdd(&g_CG[e*NE+n],       accCG[mt][0]);
            atomicAdd(&g_CG[e*NE+n+1],     accCG[mt][1]);
            atomicAdd(&g_CG[(e+8)*NE+n],   accCG[mt][2]);
            atomicAdd(&g_CG[(e+8)*NE+n+1], accCG[mt][3]);
        }
        atomicAdd(&g_Wtb[tid], accWtb);
        if (tid < 64) { atomicAdd(&g_cnormd[tid], (double)accCN); atomicAdd(&g_bcd[tid], (double)accBC); }
        if (tid == 64) atomicAdd(&g_bbd, (double)accBB);
    } else {
        // ---- Y = X @ pw1^T  (hi/lo, output-critical) ----
        float (*Xs)[36] = (float (*)[36])smp;
        float (*Bs)[36] = (float (*)[36])(smp + 9216);
        int yb = b - 384;
        int tok0 = (yb >> 2) * 64;
        int colgrp = yb & 3;
        const float* src = pw1 + (size_t)colgrp * 64 * CC;
        int wm = warp>>2, wn = warp&3;
        float acc[2][2][4];
#pragma unroll
        for (int mt=0;mt<2;mt++)
#pragma unroll
            for (int nt=0;nt<2;nt++)
#pragma unroll
                for (int q=0;q<4;q++) acc[mt][nt][q]=0.f;

        for (int ch=0; ch<8; ch++) {
            int kc = ch*32;
#pragma unroll
            for (int l=0;l<2;l++) {
                int idx = tid + l*256;
                int row = idx>>3, q = (idx&7)*4;
                float4 v = *(const float4*)(x + (size_t)(tok0+row)*CC + kc + q);
                Xs[row][q]=v.x; Xs[row][q+1]=v.y; Xs[row][q+2]=v.z; Xs[row][q+3]=v.w;
                float4 w = *(const float4*)(src + (size_t)row*CC + kc + q);
                Bs[row][q]=w.x; Bs[row][q+1]=w.y; Bs[row][q+2]=w.z; Bs[row][q+3]=w.w;
            }
            __syncthreads();
#pragma unroll
            for (int k8=0;k8<4;k8++) {
                int kb = k8*8;
                uint32_t ah[2][4], al[2][4], bh[2][2], bl[2][2];
#pragma unroll
                for (int mt=0;mt<2;mt++) {
                    int m0 = wm*32 + mt*16 + gid;
                    hilo(Xs[m0][kb+tig],     ah[mt][0], al[mt][0]);
                    hilo(Xs[m0+8][kb+tig],   ah[mt][1], al[mt][1]);
                    hilo(Xs[m0][kb+tig+4],   ah[mt][2], al[mt][2]);
                    hilo(Xs[m0+8][kb+tig+4], ah[mt][3], al[mt][3]);
                }
#pragma unroll
                for (int nt=0;nt<2;nt++) {
                    int nl = wn*16 + nt*8 + gid;
                    hilo(Bs[nl][kb+tig],   bh[nt][0], bl[nt][0]);
                    hilo(Bs[nl][kb+tig+4], bh[nt][1], bl[nt][1]);
                }
#pragma unroll
                for (int mt=0;mt<2;mt++)
#pragma unroll
                    for (int nt=0;nt<2;nt++) {
                        mma8(acc[mt][nt], ah[mt], bh[nt]);
                        mma8(acc[mt][nt], ah[mt], bl[nt]);
                        mma8(acc[mt][nt], al[mt], bh[nt]);
                    }
            }
            __syncthreads();
        }
#pragma unroll
        for (int mt=0;mt<2;mt++)
#pragma unroll
            for (int nt=0;nt<2;nt++) {
                int col = colgrp*64 + wn*16 + nt*8 + 2*tig;
#pragma unroll
                for (int rr=0;rr<2;rr++) {
                    int tok = tok0 + wm*32 + mt*16 + gid + rr*8;
                    g_Y[(size_t)tok*CC + col]   = acc[mt][nt][rr*2];
                    g_Y[(size_t)tok*CC + col+1] = acc[mt][nt][rr*2+1];
                }
            }
    }
}

// ================= phase 2 (64-token tiles): S0 from X@M | xG+softmax+binning =================
__global__ void __launch_bounds__(256) k_big2(const float* __restrict__ x,
                                              const float* __restrict__ u) {
    __shared__ __align__(16) char smp[36352];
    float (*Xs)[36] = (float (*)[36])smp;
    float (*Bs)[36] = (float (*)[36])(smp + 9216);
    float (*xgs)[68] = (float (*)[68])(smp + 18432);
    float* red = (float*)(smp + 18432);
    int b = blockIdx.x;
    int tid=threadIdx.x, warp=tid>>5, lane=tid&31, gid=lane>>2, tig=lane&3;
    int wm = warp>>2, wn = warp&3;
    int tok0, colgrp, mode;
    const float* src;
    if (b < 128) { tok0 = (b>>2)*64; colgrp = b&3; src = g_M + (size_t)colgrp*64*CC; mode=0; }
    else         { tok0 = (b-128)*64; colgrp = 0;  src = g_G; mode=1; }
    float acc[2][2][4];
#pragma unroll
    for (int mt=0;mt<2;mt++)
#pragma unroll
        for (int nt=0;nt<2;nt++)
#pragma unroll
            for (int q=0;q<4;q++) acc[mt][nt][q]=0.f;

    for (int ch=0; ch<8; ch++) {
        int kc = ch*32;
#pragma unroll
        for (int l=0;l<2;l++) {
            int idx = tid + l*256;
            int row = idx>>3, q = (idx&7)*4;
            float4 v = *(const float4*)(x + (size_t)(tok0+row)*CC + kc + q);
            Xs[row][q]=v.x; Xs[row][q+1]=v.y; Xs[row][q+2]=v.z; Xs[row][q+3]=v.w;
            float4 w = *(const float4*)(src + (size_t)row*CC + kc + q);
            Bs[row][q]=w.x; Bs[row][q+1]=w.y; Bs[row][q+2]=w.z; Bs[row][q+3]=w.w;
        }
        __syncthreads();
#pragma unroll
        for (int k8=0;k8<4;k8++) {
            int kb = k8*8;
            uint32_t ah[2][4], al[2][4], bh[2][2], bl[2][2];
#pragma unroll
            for (int mt=0;mt<2;mt++) {
                int m0 = wm*32 + mt*16 + gid;
                hilo(Xs[m0][kb+tig],     ah[mt][0], al[mt][0]);
                hilo(Xs[m0+8][kb+tig],   ah[mt][1], al[mt][1]);
                hilo(Xs[m0][kb+tig+4],   ah[mt][2], al[mt][2]);
                hilo(Xs[m0+8][kb+tig+4], ah[mt][3], al[mt][3]);
            }
#pragma unroll
            for (int nt=0;nt<2;nt++) {
                int nl = wn*16 + nt*8 + gid;
                hilo(Bs[nl][kb+tig],   bh[nt][0], bl[nt][0]);
                hilo(Bs[nl][kb+tig+4], bh[nt][1], bl[nt][1]);
            }
#pragma unroll
            for (int mt=0;mt<2;mt++)
#pragma unroll
                for (int nt=0;nt<2;nt++) {
                    mma8(acc[mt][nt], ah[mt], bh[nt]);
                    mma8(acc[mt][nt], ah[mt], bl[nt]);
                    mma8(acc[mt][nt], al[mt], bh[nt]);
                }
        }
        __syncthreads();
    }
    if (mode == 0) {
        float s0 = 0.f;
#pragma unroll
        for (int mt=0;mt<2;mt++)
#pragma unroll
            for (int nt=0;nt<2;nt++) {
                int col = colgrp*64 + wn*16 + nt*8 + 2*tig;
#pragma unroll
                for (int rr=0;rr<2;rr++) {
                    int tok = tok0 + wm*32 + mt*16 + gid + rr*8;
                    s0 += acc[mt][nt][rr*2]   * x[(size_t)tok*CC + col];
                    s0 += acc[mt][nt][rr*2+1] * x[(size_t)tok*CC + col+1];
                }
            }
        red[tid] = s0; __syncthreads();
        for (int s=128;s>=1;s>>=1) { if (tid<s) red[tid]+=red[tid+s]; __syncthreads(); }
        if (tid == 0) atomicAdd(&g_accd[0], (double)red[0]);
        return;
    }
#pragma unroll
    for (int mt=0;mt<2;mt++)
#pragma unroll
        for (int nt=0;nt<2;nt++) {
            int col = wn*16 + nt*8 + 2*tig;
#pragma unroll
            for (int rr=0;rr<2;rr++) {
                int lt = wm*32 + mt*16 + gid + rr*8;
                xgs[lt][col]   = acc[mt][nt][rr*2];
                xgs[lt][col+1] = acc[mt][nt][rr*2+1];
            }
        }
    __syncthreads();
    float cn0 = (float)g_cnormd[lane], cn1 = (float)g_cnormd[lane+32];
    float bc0 = (float)g_bcd[lane],    bc1 = (float)g_bcd[lane+32];
    float s1acc = 0.f;
    for (int k=0;k<8;k++) {
        int lt = warp*8 + k;
        size_t n = tok0 + lt;
        float xg0 = xgs[lt][lane]    + bc0;
        float xg1 = xgs[lt][lane+32] + bc1;
        float l0 = 2.f*xg0 - cn0 - logf(-logf(u[n*NE+lane]));
        float l1 = 2.f*xg1 - cn1 - logf(-logf(u[n*NE+lane+32]));
        float m = fmaxf(l0, l1);
#pragma unroll
        for (int o=16;o>=1;o>>=1) m = fmaxf(m, __shfl_xor_sync(0xffffffffu, m, o));
        float ex0 = expf(l0 - m), ex1 = expf(l1 - m);
        float S = ex0 + ex1;
#pragma unroll
        for (int o=16;o>=1;o>>=1) S += __shfl_xor_sync(0xffffffffu, S, o);
        float r0 = ex0 / S, r1 = ex1 / S;
        g_resp[n*NE+lane]    = r0;
        g_resp[n*NE+lane+32] = r1;
        float s1 = r0*xg0 + r1*xg1;
#pragma unroll
        for (int o=16;o>=1;o>>=1) s1 += __shfl_xor_sync(0xffffffffu, s1, o);
        if (lane == 0) s1acc += s1;
        if (r0 > 1e-9f) {
            int p = atomicAdd(&g_cnt[lane], 1);
            g_tokn[lane*NN+p] = (int)n; g_tokr[lane*NN+p] = r0;
        }
        if (r1 > 1e-9f) {
            int p = atomicAdd(&g_cnt[lane+32], 1);
            g_tokn[(lane+32)*NN+p] = (int)n; g_tokr[(lane+32)*NN+p] = r1;
        }
    }
    if (lane == 0) atomicAdd(&g_accd[1], (double)s1acc);
}

// ================= A=R^T X (plain), Q=R^T R (hi/lo), s, xsum  (32 tokens/blk) =================
__global__ void __launch_bounds__(256) k_RX(const float* __restrict__ x) {
    __shared__ float Rs[32][68];
    __shared__ float Xs[32][260];
    int tid=threadIdx.x, warp=tid>>5, lane=tid&31, gid=lane>>2, tig=lane&3;
    int nb = blockIdx.x * 32;
    float accA[4][4][4], accQ[4][4];
#pragma unroll
    for (int mt=0;mt<4;mt++) {
#pragma unroll
        for (int nt=0;nt<4;nt++)
#pragma unroll
            for (int q=0;q<4;q++) accA[mt][nt][q]=0.f;
#pragma unroll
        for (int q=0;q<4;q++) accQ[mt][q]=0.f;
    }
    float sp=0.f, xsacc=0.f;

#pragma unroll
    for (int l=0;l<8;l++) {
        int idx = tid + l*256;
        int row = idx>>6, e2 = idx&63;
        Rs[row][e2] = g_resp[(size_t)(nb+row)*NE + e2];
    }
#pragma unroll
    for (int l=0;l<8;l++) {
        int idx = tid + l*256;
        int row = idx>>6, q = (idx&63)*4;
        float4 v = *(const float4*)(x + (size_t)(nb+row)*CC + q);
        Xs[row][q]=v.x; Xs[row][q+1]=v.y; Xs[row][q+2]=v.z; Xs[row][q+3]=v.w;
    }
    __syncthreads();
    if (tid < 64) {
        for (int k=0;k<32;k++) sp += Rs[k][tid];
    }
    for (int k=0;k<32;k++) xsacc += Xs[k][tid];
#pragma unroll
    for (int k8=0;k8<4;k8++) {
        int kb = k8*8;
        uint32_t am[4][4], amh[4][4], aml[4][4];
#pragma unroll
        for (int mt=0;mt<4;mt++) {
            int m0 = mt*16;
            float v0 = Rs[kb+tig][m0+gid],   v1 = Rs[kb+tig][m0+gid+8];
            float v2 = Rs[kb+tig+4][m0+gid], v3 = Rs[kb+tig+4][m0+gid+8];
            am[mt][0]=fb(v0); am[mt][1]=fb(v1); am[mt][2]=fb(v2); am[mt][3]=fb(v3);
            hilo(v0, amh[mt][0], aml[mt][0]); hilo(v1, amh[mt][1], aml[mt][1]);
            hilo(v2, amh[mt][2], aml[mt][2]); hilo(v3, amh[mt][3], aml[mt][3]);
        }
#pragma unroll
        for (int nt=0;nt<4;nt++) {
            int c = warp*32 + nt*8 + gid;
            uint32_t bx[2] = { fb(Xs[kb+tig][c]), fb(Xs[kb+tig+4][c]) };
#pragma unroll
            for (int mt=0;mt<4;mt++) mma8(accA[mt][nt], am[mt], bx);
        }
        {
            int eq = warp*8 + gid;
            uint32_t bqh[2], bql[2];
            hilo(Rs[kb+tig][eq],   bqh[0], bql[0]);
            hilo(Rs[kb+tig+4][eq], bqh[1], bql[1]);
#pragma unroll
            for (int mt=0;mt<4;mt++) {
                mma8(accQ[mt], amh[mt], bqh);
                mma8(accQ[mt], amh[mt], bql);
                mma8(accQ[mt], aml[mt], bqh);
            }
        }
    }
#pragma unroll
    for (int mt=0;mt<4;mt++) {
#pragma unroll
        for (int nt=0;nt<4;nt++) {
            int e = mt*16 + gid;
            int c = warp*32 + nt*8 + 2*tig;
            atomicAdd(&g_A[e*CC+c],        accA[mt][nt][0]);
            atomicAdd(&g_A[e*CC+c+1],      accA[mt][nt][1]);
            atomicAdd(&g_A[(e+8)*CC+c],    accA[mt][nt][2]);
            atomicAdd(&g_A[(e+8)*CC+c+1],  accA[mt][nt][3]);
        }
        int e = mt*16 + gid;
        int eq = warp*8 + 2*tig;
        atomicAdd(&g_Q[e*NE+eq],       accQ[mt][0]);
        atomicAdd(&g_Q[e*NE+eq+1],     accQ[mt][1]);
        atomicAdd(&g_Q[(e+8)*NE+eq],   accQ[mt][2]);
        atomicAdd(&g_Q[(e+8)*NE+eq+1], accQ[mt][3]);
    }
    if (tid < 64) atomicAdd(&g_s[tid], sp);
    atomicAdd(&g_xsum[tid], xsacc);
}

// ================= Cnew bf16 (512 blks) | loss contractions (64 blks) =================
__global__ void __launch_bounds__(256) k_cnew(const float* __restrict__ W,
                                              const float* __restrict__ cents,
                                              const float* __restrict__ bvec) {
    int tid=threadIdx.x, warp=tid>>5, lane=tid&31, gid=lane>>2, tig=lane&3;
    if (blockIdx.x >= 512) {
        int e = blockIdx.x - 512;
        __shared__ float As[256];
        __shared__ float red[256];
        As[tid] = g_A[e*CC + tid];
        __syncthreads();
        float uv = 0.f;
        for (int e2=0;e2<NE;e2++) uv += g_Q[e*NE+e2] * g_A[e2*CC + tid];
        float am = 0.f;
        for (int c=0;c<CC;c++) am += As[c] * g_M[c*CC + tid];
        float a = As[tid];
        float ge = g_G[e*CC + tid];
        float wtb = g_Wtb[tid];

        float r1, r2, r3, r4, r5, r6;
        red[tid] = am*a; __syncthreads();
        for (int s=128;s>=1;s>>=1) { if (tid<s) red[tid]+=red[tid+s]; __syncthreads(); }
        r1 = red[0]; __syncthreads();
        red[tid] = a*wtb; __syncthreads();
        for (int s=128;s>=1;s>>=1) { if (tid<s) red[tid]+=red[tid+s]; __syncthreads(); }
        r2 = red[0]; __syncthreads();
        red[tid] = ge*uv; __syncthreads();
        for (int s=128;s>=1;s>>=1) { if (tid<s) red[tid]+=red[tid+s]; __syncthreads(); }
        r3 = red[0]; __syncthreads();
        red[tid] = am*uv; __syncthreads();
        for (int s=128;s>=1;s>>=1) { if (tid<s) red[tid]+=red[tid+s]; __syncthreads(); }
        r4 = red[0]; __syncthreads();
        red[tid] = (tid < NE) ? g_Q[e*NE+tid]*g_s[tid] : 0.f; __syncthreads();
        for (int s=128;s>=1;s>>=1) { if (tid<s) red[tid]+=red[tid+s]; __syncthreads(); }
        r5 = red[0]; __syncthreads();
        red[tid] = (tid < NE) ? g_CG[e*NE+tid]*g_Q[e*NE+tid] : 0.f; __syncthreads();
        for (int s=128;s>=1;s>>=1) { if (tid<s) red[tid]+=red[tid+s]; __syncthreads(); }
        r6 = red[0]; __syncthreads();

        if (tid == 0) {
            double se = (double)g_s[e];
            double bb = g_bbd;
            double bce = g_bcd[e];
            double d = 0.999, gam = (double)GAMv;
            double p_e = (double)r1 + 2.0*se*(double)r2 + bb*se*se;
            double quad_e = d*d*(double)r6
                          + 2.0*d*gam*((double)r3 + bce*(double)r5)
                          + gam*gam*((double)r4 + 2.0*(double)r2*(double)r5 + bb*se*(double)r5);
            atomicAdd(&g_accd[2], p_e);
            atomicAdd(&g_accd[3], quad_e);
        }
        if (e == 0) {
            red[tid] = 2.f*g_xsum[tid]*g_Wtb[tid]; __syncthreads();
            for (int s=128;s>=1;s>>=1) { if (tid<s) red[tid]+=red[tid+s]; __syncthreads(); }
            if (tid == 0) atomicAdd(&g_accd[0], (double)red[0] + (double)NN * g_bbd);
        }
        return;
    }
    // ---- Cnew = decay*Cents + gam*(A@W^T + s b^T), bf16 m16n8k16 ----
    __shared__ uint32_t Apk[16][68];
    __shared__ uint32_t Wpk[16][132];
    __shared__ float ss[64];
    int d0 = blockIdx.x * 128;
    if (tid < 64) ss[tid] = g_s[tid];
    float acc[4][2][4];
#pragma unroll
    for (int mt=0;mt<4;mt++)
#pragma unroll
        for (int nt=0;nt<2;nt++)
#pragma unroll
            for (int q=0;q<4;q++) acc[mt][nt][q]=0.f;

    for (int ch=0; ch<8; ch++) {
        int kc = ch*32;
#pragma unroll
        for (int l=0;l<2;l++) {
            int idx = tid + l*256;
            int e = idx>>3, q = (idx&7)*4;
            float4 v = *(const float4*)(g_A + (size_t)e*CC + kc + q);
            Apk[q>>1][e]     = pk2(v.x, v.y);
            Apk[(q>>1)+1][e] = pk2(v.z, v.w);
        }
#pragma unroll
        for (int l=0;l<4;l++) {
            int idx = tid + l*256;
            int row = idx>>3, q = (idx&7)*4;
            float4 v = *(const float4*)(W + (size_t)(d0+row)*CC + kc + q);
            Wpk[q>>1][row]     = pk2(v.x, v.y);
            Wpk[(q>>1)+1][row] = pk2(v.z, v.w);
        }
        __syncthreads();
#pragma unroll
        for (int kpb=0; kpb<16; kpb+=8) {
            uint32_t a[4][4], b[2][2];
#pragma unroll
            for (int mt=0;mt<4;mt++) {
                int e = mt*16 + gid;
                a[mt][0]=Apk[kpb+tig][e];
                a[mt][1]=Apk[kpb+tig][e+8];
                a[mt][2]=Apk[kpb+tig+4][e];
                a[mt][3]=Apk[kpb+tig+4][e+8];
            }
#pragma unroll
            for (int nt=0;nt<2;nt++) {
                int dl = warp*16 + nt*8 + gid;
                b[nt][0]=Wpk[kpb+tig][dl];
                b[nt][1]=Wpk[kpb+tig+4][dl];
            }
#pragma unroll
            for (int mt=0;mt<4;mt++)
#pragma unroll
                for (int nt=0;nt<2;nt++) mma16bf(acc[mt][nt], a[mt], b[nt]);
        }
        __syncthreads();
    }
#pragma unroll
    for (int mt=0;mt<4;mt++)
#pragma unroll
        for (int nt=0;nt<2;nt++) {
            int e = mt*16 + gid;
            int d = d0 + warp*16 + nt*8 + 2*tig;
            float b0 = bvec[d], b1 = bvec[d+1];
            g_Cnew[(size_t)e*DD+d]       = DECAYv*cents[(size_t)e*DD+d]       + GAMv*(acc[mt][nt][0] + ss[e]*b0);
            g_Cnew[(size_t)e*DD+d+1]     = DECAYv*cents[(size_t)e*DD+d+1]     + GAMv*(acc[mt][nt][1] + ss[e]*b1);
            g_Cnew[(size_t)(e+8)*DD+d]   = DECAYv*cents[(size_t)(e+8)*DD+d]   + GAMv*(acc[mt][nt][2] + ss[e+8]*b0);
            g_Cnew[(size_t)(e+8)*DD+d+1] = DECAYv*cents[(size_t)(e+8)*DD+d+1] + GAMv*(acc[mt][nt][3] + ss[e+8]*b1);
        }
}

// ================= binned output GEMM (hi/lo), persistent 8 slots/expert =================
__global__ void __launch_bounds__(256) k_out(float* __restrict__ out) {
    __shared__ __align__(16) char smp[70400];
    int b = blockIdx.x;
    int tid=threadIdx.x, warp=tid>>5, lane=tid&31, gid=lane>>2, tig=lane&3;
    int e = b & 63;
    int cnt = g_cnt[e];
    float (*ys)[260] = (float (*)[260])smp;
    float (*Cw)[36]  = (float (*)[36])(smp + 33280);
    int* stok        = (int*)(smp + 33280 + 36864);
    int wm = warp>>2, wn = warp&3;

    for (int a0 = (b >> 6) * 32; a0 < cnt; a0 += 256) {
#pragma unroll
        for (int l=0;l<8;l++) {
            int idx = tid + l*256;
            int row = idx >> 6, q = idx & 63;
            int aa = a0 + row;
            float r = 0.f; int n = 0;
            float4 v = make_float4(0.f,0.f,0.f,0.f);
            if (aa < cnt) {
                n = g_tokn[e*NN+aa]; r = g_tokr[e*NN+aa];
                v = *(const float4*)(g_Y + (size_t)n*CC + q*4);
            }
            ys[row][q*4]=r*v.x; ys[row][q*4+1]=r*v.y; ys[row][q*4+2]=r*v.z; ys[row][q*4+3]=r*v.w;
            if (q == 0) stok[row] = n;
        }
        __syncthreads();
        float acc[8][4];
#pragma unroll
        for (int nt=0;nt<8;nt++)
#pragma unroll
            for (int q=0;q<4;q++) acc[nt][q]=0.f;

        for (int ch=0; ch<8; ch++) {
            int kc = ch*32;
#pragma unroll
            for (int l=0;l<8;l++) {
                int idx = tid + l*256;
                int row = idx >> 3, q = (idx & 7)*4;
                float4 v = *(const float4*)(g_Cnew + (size_t)e*DD + (size_t)row*CC + kc + q);
                Cw[row][q]=v.x; Cw[row][q+1]=v.y; Cw[row][q+2]=v.z; Cw[row][q+3]=v.w;
            }
            __syncthreads();
#pragma unroll
            for (int k8=0;k8<4;k8++) {
                int kb = k8*8;
                uint32_t ah[4], al[4];
                int m0 = wm*16 + gid;
                hilo(ys[m0][kc+kb+tig],     ah[0], al[0]);
                hilo(ys[m0+8][kc+kb+tig],   ah[1], al[1]);
                hilo(ys[m0][kc+kb+tig+4],   ah[2], al[2]);
                hilo(ys[m0+8][kc+kb+tig+4], ah[3], al[3]);
#pragma unroll
                for (int nt=0;nt<8;nt++) {
                    int nc = wn*64 + nt*8 + gid;
                    uint32_t bh[2], bl[2];
                    hilo(Cw[nc][kb+tig],   bh[0], bl[0]);
                    hilo(Cw[nc][kb+tig+4], bh[1], bl[1]);
                    mma8(acc[nt], ah, bh);
                    mma8(acc[nt], ah, bl);
                    mma8(acc[nt], al, bh);
                }
            }
            __syncthreads();
        }
        int t0 = wm*16 + gid;
        int r0 = stok[t0], r1 = stok[t0+8];
#pragma unroll
        for (int nt=0;nt<8;nt++) {
            int i = wn*64 + nt*8 + 2*tig;
            atomicAdd(out + (size_t)r0*ROUT + i,   acc[nt][0]);
            atomicAdd(out + (size_t)r0*ROUT + i+1, acc[nt][1]);
            atomicAdd(out + (size_t)r1*ROUT + i,   acc[nt][2]);
            atomicAdd(out + (size_t)r1*ROUT + i+1, acc[nt][3]);
        }
        __syncthreads();
    }
}

// ================= final: bias | loss scalar =================
__global__ void k_fin(float* __restrict__ out, const float* __restrict__ pwB, int out_size) {
    int b = blockIdx.x, tid = threadIdx.x;
    if (b < NN) {
        out[(size_t)b*ROUT + tid] += pwB[tid];
        return;
    }
    double S1 = 0.999*g_accd[1] + (double)GAMv*g_accd[2];
    double loss = 0.25*(g_accd[0] - 2.0*S1 + g_accd[3]) / ((double)NN * (double)DD);
    float lf = (float)loss;
    for (int i = NN*ROUT + tid; i < out_size; i += 256) out[i] = lf;
}

extern "C" void kernel_launch(void* const* d_in, const int* in_sizes, int n_in,
                              void* d_out, int out_size) {
    const float* x     = (const float*)d_in[0];
    const float* u     = (const float*)d_in[1];
    const float* W     = (const float*)d_in[2];
    const float* bvec  = (const float*)d_in[3];
    const float* pw1   = (const float*)d_in[4];
    const float* pwB   = (const float*)d_in[5];
    const float* cents = (const float*)d_in[6];
    float* out = (float*)d_out;

    k_zero<<<2048, 256>>>(out);
    k_p1<<<512, 256>>>(W, cents, bvec, x, pw1);
    k_big2<<<160, 256>>>(x, u);
    k_RX<<<64, 256>>>(x);
    k_cnew<<<576, 256>>>(W, cents, bvec);
    k_out<<<512, 256>>>(out);
    k_fin<<<NN + 1, 256>>>(out, pwB, out_size);
}

// round 13
// speedup vs baseline: 1.1202x; 1.0189x over previous
#include <cuda_runtime.h>
#include <cuda_bf16.h>
#include <math.h>
#include <stdint.h>

#define CC 256
#define NN 2048
#define DD 65536
#define NE 64
#define ROUT 256
#define DECAYv 0.999f
#define GAMv 4.8828125e-7f
#define COMMITv 0.25f

__device__ float g_M[CC*CC];
__device__ float g_G[NE*CC];
__device__ float g_A[NE*CC];
__device__ float g_Q[NE*NE];
__device__ float g_CG[NE*NE];
__device__ double g_cnormd[NE], g_bcd[NE], g_bbd;
__device__ float g_s[NE];
__device__ float g_Wtb[CC];
__device__ float g_xsum[CC];
__device__ double g_accd[4];      // 0:S0  1:S1a  2:p  3:quad
__device__ float g_Y[NN*CC];
__device__ float g_resp[NN*NE];
__device__ int   g_cnt[NE];
__device__ int   g_tokn[NE*NN];
__device__ float g_tokr[NE*NN];
__device__ float g_Cnew[NE*DD];

__device__ __forceinline__ void mma8(float* c, const uint32_t* a, const uint32_t* b) {
    asm volatile("mma.sync.aligned.m16n8k8.row.col.f32.tf32.tf32.f32 "
        "{%0,%1,%2,%3}, {%4,%5,%6,%7}, {%8,%9}, {%0,%1,%2,%3};"
        : "+f"(c[0]), "+f"(c[1]), "+f"(c[2]), "+f"(c[3])
        : "r"(a[0]), "r"(a[1]), "r"(a[2]), "r"(a[3]), "r"(b[0]), "r"(b[1]));
}
__device__ __forceinline__ void mma16bf(float* c, const uint32_t* a, const uint32_t* b) {
    asm volatile("mma.sync.aligned.m16n8k16.row.col.f32.bf16.bf16.f32 "
        "{%0,%1,%2,%3}, {%4,%5,%6,%7}, {%8,%9}, {%0,%1,%2,%3};"
        : "+f"(c[0]), "+f"(c[1]), "+f"(c[2]), "+f"(c[3])
        : "r"(a[0]), "r"(a[1]), "r"(a[2]), "r"(a[3]), "r"(b[0]), "r"(b[1]));
}
__device__ __forceinline__ uint32_t fb(float x) { return __float_as_uint(x); }
__device__ __forceinline__ uint32_t pk2(float a, float b) {
    __nv_bfloat162 p = __floats2bfloat162_rn(a, b);
    return *(uint32_t*)&p;
}
// bf16 hi/lo split of a float pair, packed along k
__device__ __forceinline__ void pkhl(float v0, float v1, uint32_t& h, uint32_t& l) {
    __nv_bfloat16 h0 = __float2bfloat16(v0);
    __nv_bfloat16 h1 = __float2bfloat16(v1);
    float l0 = v0 - __bfloat162float(h0);
    float l1 = v1 - __bfloat162float(h1);
    __nv_bfloat162 hh; hh.x = h0; hh.y = h1;
    h = *(uint32_t*)&hh;
    l = pk2(l0, l1);
}
__device__ __forceinline__ void hilo(float v, uint32_t& h, uint32_t& l) {
    uint32_t hb = __float_as_uint(v) & 0xFFFFE000u;
    h = hb;
    l = fb(v - __uint_as_float(hb));
}

// ================= zero =================
__global__ void k_zero(float* __restrict__ out) {
    int i = blockIdx.x * 256 + threadIdx.x;
    if (i < NN*ROUT) out[i] = 0.f;
    if (i < CC*CC) g_M[i] = 0.f;
    if (i < NE*CC) { g_G[i]=0.f; g_A[i]=0.f; }
    if (i < NE*NE) { g_Q[i]=0.f; g_CG[i]=0.f; }
    if (i < CC) { g_Wtb[i] = 0.f; g_xsum[i] = 0.f; }
    if (i < NE) { g_cnormd[i]=0.0; g_bcd[i]=0.0; g_s[i]=0.f; g_cnt[i]=0; }
    if (i < 4) g_accd[i] = 0.0;
    if (i == 4) g_bbd = 0.0;
}

// ================= phase 1: gram(M bf16,128) | centW(G hi/lo + CG bf16, 256) | Y(bf16-hilo,128) =================
__global__ void __launch_bounds__(256) k_p1(const float* __restrict__ W,
                                            const float* __restrict__ cents,
                                            const float* __restrict__ bvec,
                                            const float* __restrict__ x,
                                            const float* __restrict__ pw1) {
    __shared__ __align__(16) char smp[47104];
    int b = blockIdx.x;
    int tid=threadIdx.x, warp=tid>>5, lane=tid&31, gid=lane>>2, tig=lane&3;

    if (b < 128) {
        // ---- gram: M = W^T W in bf16 m16n8k16 (loss-only path) ----
        uint32_t (*Wp)[260] = (uint32_t (*)[260])smp;
        int wm = warp>>2, wn = warp&3;
        int i0 = (b & 1) * 128;
        int d0 = (b >> 1) * 1024;
        float acc[4][8][4];
#pragma unroll
        for (int mt=0;mt<4;mt++)
#pragma unroll
            for (int nt=0;nt<8;nt++)
#pragma unroll
                for (int q=0;q<4;q++) acc[mt][nt][q]=0.f;

        for (int ch=0; ch<32; ch++) {
            int drow = d0 + ch*32;
#pragma unroll
            for (int l=0;l<16;l++) {
                int idx = tid + l*256;
                int kp = idx >> 8, c = idx & 255;
                float v0 = W[(size_t)(drow + 2*kp)   * CC + c];
                float v1 = W[(size_t)(drow + 2*kp+1) * CC + c];
                Wp[kp][c] = pk2(v0, v1);
            }
            __syncthreads();
#pragma unroll
            for (int st=0; st<2; st++) {
                int kpb = st*8;
                uint32_t a[4][4];
#pragma unroll
                for (int mt=0;mt<4;mt++) {
                    int ib = i0 + wm*64 + mt*16 + gid;
                    a[mt][0]=Wp[kpb+tig][ib];
                    a[mt][1]=Wp[kpb+tig][ib+8];
                    a[mt][2]=Wp[kpb+tig+4][ib];
                    a[mt][3]=Wp[kpb+tig+4][ib+8];
                }
#pragma unroll
                for (int nt=0;nt<8;nt++) {
                    int jb = wn*64 + nt*8 + gid;
                    uint32_t bv[2] = { Wp[kpb+tig][jb], Wp[kpb+tig+4][jb] };
#pragma unroll
                    for (int mt=0;mt<4;mt++) mma16bf(acc[mt][nt], a[mt], bv);
                }
            }
            __syncthreads();
        }
#pragma unroll
        for (int mt=0;mt<4;mt++)
#pragma unroll
            for (int nt=0;nt<8;nt++) {
                int i = i0 + wm*64 + mt*16 + gid;
                int j = wn*64 + nt*8 + 2*tig;
                atomicAdd(&g_M[i*CC+j],       acc[mt][nt][0]);
                atomicAdd(&g_M[i*CC+j+1],     acc[mt][nt][1]);
                atomicAdd(&g_M[(i+8)*CC+j],   acc[mt][nt][2]);
                atomicAdd(&g_M[(i+8)*CC+j+1], acc[mt][nt][3]);
            }
    } else if (b < 384) {
        // ---- centW: G hi/lo (routing) + CG bf16 (loss) + cnorm/bc/Wtb/bb ----
        float (*Cs)[36]  = (float (*)[36])smp;                       // 9216
        float (*Ws)[260] = (float (*)[260])(smp + 9216);             // 33280
        uint32_t (*Cpk)[68] = (uint32_t (*)[68])(smp + 42496);       // 4352
        float* bs        = (float*)(smp + 46848);                    // 128
        int blk = b - 128;
        int d0 = blk * 256;
        float accG[4][4][4], accCG[4][4];
#pragma unroll
        for (int mt=0;mt<4;mt++) {
#pragma unroll
            for (int nt=0;nt<4;nt++)
#pragma unroll
                for (int q=0;q<4;q++) accG[mt][nt][q]=0.f;
#pragma unroll
            for (int q=0;q<4;q++) accCG[mt][q]=0.f;
        }
        float accWtb=0.f, accCN=0.f, accBC=0.f, accBB=0.f;

        for (int ch=0; ch<8; ch++) {
            int dbase = d0 + ch*32;
#pragma unroll
            for (int l=0;l<2;l++) {
                int idx = tid + l*256;
                int e = idx>>3, q = (idx&7)*4;
                float4 v = *(const float4*)(cents + (size_t)e*DD + dbase + q);
                Cs[e][q]=v.x; Cs[e][q+1]=v.y; Cs[e][q+2]=v.z; Cs[e][q+3]=v.w;
                Cpk[q>>1][e]     = pk2(v.x, v.y);
                Cpk[(q>>1)+1][e] = pk2(v.z, v.w);
            }
#pragma unroll
            for (int l=0;l<8;l++) {
                int idx = tid + l*256;
                int row = idx>>6, q = (idx&63)*4;
                float4 v = *(const float4*)(W + (size_t)(dbase+row)*CC + q);
                Ws[row][q]=v.x; Ws[row][q+1]=v.y; Ws[row][q+2]=v.z; Ws[row][q+3]=v.w;
            }
            if (tid < 32) bs[tid] = bvec[dbase + tid];
            __syncthreads();
            {
                float aw = 0.f;
                for (int k=0;k<32;k++) aw += bs[k]*Ws[k][tid];
                accWtb += aw;
            }
            if (tid < 64) {
                float cn=0.f, bc=0.f;
                for (int k=0;k<32;k++) { float c=Cs[tid][k]; cn+=c*c; bc+=c*bs[k]; }
                accCN += cn; accBC += bc;
            }
            if (tid == 64) {
                float sb=0.f;
                for (int k=0;k<32;k++) sb += bs[k]*bs[k];
                accBB += sb;
            }
            // G: full hi/lo tf32 (routing-critical)
#pragma unroll
            for (int k8=0;k8<4;k8++) {
                int kb = k8*8;
                uint32_t ah[4][4], al[4][4];
#pragma unroll
                for (int mt=0;mt<4;mt++) {
                    int e = mt*16 + gid;
                    hilo(Cs[e][kb+tig],     ah[mt][0], al[mt][0]);
                    hilo(Cs[e+8][kb+tig],   ah[mt][1], al[mt][1]);
                    hilo(Cs[e][kb+tig+4],   ah[mt][2], al[mt][2]);
                    hilo(Cs[e+8][kb+tig+4], ah[mt][3], al[mt][3]);
                }
#pragma unroll
                for (int nt=0;nt<4;nt++) {
                    int c = warp*32 + nt*8 + gid;
                    uint32_t bh[2], bl[2];
                    hilo(Ws[kb+tig][c],   bh[0], bl[0]);
                    hilo(Ws[kb+tig+4][c], bh[1], bl[1]);
#pragma unroll
                    for (int mt=0;mt<4;mt++) {
                        mma8(accG[mt][nt], ah[mt], bh);
                        mma8(accG[mt][nt], ah[mt], bl);
                        mma8(accG[mt][nt], al[mt], bh);
                    }
                }
            }
            // CG: bf16 m16n8k16 (loss-only)
#pragma unroll
            for (int kpb=0; kpb<16; kpb+=8) {
                uint32_t a[4][4], bcg[2];
#pragma unroll
                for (int mt=0;mt<4;mt++) {
                    int e = mt*16 + gid;
                    a[mt][0]=Cpk[kpb+tig][e];
                    a[mt][1]=Cpk[kpb+tig][e+8];
                    a[mt][2]=Cpk[kpb+tig+4][e];
                    a[mt][3]=Cpk[kpb+tig+4][e+8];
                }
                int n0q = warp*8 + gid;
                bcg[0]=Cpk[kpb+tig][n0q];
                bcg[1]=Cpk[kpb+tig+4][n0q];
#pragma unroll
                for (int mt=0;mt<4;mt++) mma16bf(accCG[mt], a[mt], bcg);
            }
            __syncthreads();
        }
#pragma unroll
        for (int mt=0;mt<4;mt++) {
#pragma unroll
            for (int nt=0;nt<4;nt++) {
                int e = mt*16 + gid;
                int c = warp*32 + nt*8 + 2*tig;
                atomicAdd(&g_G[e*CC+c],       accG[mt][nt][0]);
                atomicAdd(&g_G[e*CC+c+1],     accG[mt][nt][1]);
                atomicAdd(&g_G[(e+8)*CC+c],   accG[mt][nt][2]);
                atomicAdd(&g_G[(e+8)*CC+c+1], accG[mt][nt][3]);
            }
            int e = mt*16 + gid;
            int n = warp*8 + 2*tig;
            atomicAdd(&g_CG[e*NE+n],       accCG[mt][0]);
            atomicAdd(&g_CG[e*NE+n+1],     accCG[mt][1]);
            atomicAdd(&g_CG[(e+8)*NE+n],   accCG[mt][2]);
            atomicAdd(&g_CG[(e+8)*NE+n+1], accCG[mt][3]);
        }
        atomicAdd(&g_Wtb[tid], accWtb);
        if (tid < 64) { atomicAdd(&g_cnormd[tid], (double)accCN); atomicAdd(&g_bcd[tid], (double)accBC); }
        if (tid == 64) atomicAdd(&g_bbd, (double)accBB);
    } else {
        // ---- Y = X @ pw1^T  (bf16 hi/lo, output-precision) ----
        float (*Xs)[36] = (float (*)[36])smp;
        float (*Bs)[36] = (float (*)[36])(smp + 9216);
        int yb = b - 384;
        int tok0 = (yb >> 2) * 64;
        int colgrp = yb & 3;
        const float* src = pw1 + (size_t)colgrp * 64 * CC;
        int wm = warp>>2, wn = warp&3;
        float acc[2][2][4];
#pragma unroll
        for (int mt=0;mt<2;mt++)
#pragma unroll
            for (int nt=0;nt<2;nt++)
#pragma unroll
                for (int q=0;q<4;q++) acc[mt][nt][q]=0.f;

        for (int ch=0; ch<8; ch++) {
            int kc = ch*32;
#pragma unroll
            for (int l=0;l<2;l++) {
                int idx = tid + l*256;
                int row = idx>>3, q = (idx&7)*4;
                float4 v = *(const float4*)(x + (size_t)(tok0+row)*CC + kc + q);
                Xs[row][q]=v.x; Xs[row][q+1]=v.y; Xs[row][q+2]=v.z; Xs[row][q+3]=v.w;
                float4 w = *(const float4*)(src + (size_t)row*CC + kc + q);
                Bs[row][q]=w.x; Bs[row][q+1]=w.y; Bs[row][q+2]=w.z; Bs[row][q+3]=w.w;
            }
            __syncthreads();
#pragma unroll
            for (int kpb=0; kpb<16; kpb+=8) {
                uint32_t ah[2][4], al[2][4], bh[2][2], bl[2][2];
#pragma unroll
                for (int mt=0;mt<2;mt++) {
                    int m0 = wm*32 + mt*16 + gid;
                    int k0 = 2*(kpb+tig), k1 = 2*(kpb+tig+4);
                    pkhl(Xs[m0][k0],   Xs[m0][k0+1],   ah[mt][0], al[mt][0]);
                    pkhl(Xs[m0+8][k0], Xs[m0+8][k0+1], ah[mt][1], al[mt][1]);
                    pkhl(Xs[m0][k1],   Xs[m0][k1+1],   ah[mt][2], al[mt][2]);
                    pkhl(Xs[m0+8][k1], Xs[m0+8][k1+1], ah[mt][3], al[mt][3]);
                }
#pragma unroll
                for (int nt=0;nt<2;nt++) {
                    int nl = wn*16 + nt*8 + gid;
                    int k0 = 2*(kpb+tig), k1 = 2*(kpb+tig+4);
                    pkhl(Bs[nl][k0], Bs[nl][k0+1], bh[nt][0], bl[nt][0]);
                    pkhl(Bs[nl][k1], Bs[nl][k1+1], bh[nt][1], bl[nt][1]);
                }
#pragma unroll
                for (int mt=0;mt<2;mt++)
#pragma unroll
                    for (int nt=0;nt<2;nt++) {
                        mma16bf(acc[mt][nt], ah[mt], bh[nt]);
                        mma16bf(acc[mt][nt], ah[mt], bl[nt]);
                        mma16bf(acc[mt][nt], al[mt], bh[nt]);
                    }
            }
            __syncthreads();
        }
#pragma unroll
        for (int mt=0;mt<2;mt++)
#pragma unroll
            for (int nt=0;nt<2;nt++) {
                int col = colgrp*64 + wn*16 + nt*8 + 2*tig;
#pragma unroll
                for (int rr=0;rr<2;rr++) {
                    int tok = tok0 + wm*32 + mt*16 + gid + rr*8;
                    g_Y[(size_t)tok*CC + col]   = acc[mt][nt][rr*2];
                    g_Y[(size_t)tok*CC + col+1] = acc[mt][nt][rr*2+1];
                }
            }
    }
}

// ================= phase 2: S0 (plain bf16) | xG tf32-hilo + softmax + binning =================
__global__ void __launch_bounds__(256) k_big2(const float* __restrict__ x,
                                              const float* __restrict__ u) {
    __shared__ __align__(16) char smp[36352];
    int b = blockIdx.x;
    int tid=threadIdx.x, warp=tid>>5, lane=tid&31, gid=lane>>2, tig=lane&3;
    int wm = warp>>2, wn = warp&3;

    if (b < 128) {
        // ---- mode 0: S0 partial from X@M, plain bf16 (loss-only) ----
        uint32_t (*Xpk)[68] = (uint32_t (*)[68])smp;          // 4352
        uint32_t (*Mpk)[68] = (uint32_t (*)[68])(smp + 4352); // 4352
        float* red = (float*)(smp + 8704);
        int tok0 = (b>>2)*64;
        int colgrp = b&3;
        const float* src = g_M + (size_t)colgrp*64*CC;
        float acc[2][2][4];
#pragma unroll
        for (int mt=0;mt<2;mt++)
#pragma unroll
            for (int nt=0;nt<2;nt++)
#pragma unroll
                for (int q=0;q<4;q++) acc[mt][nt][q]=0.f;

        for (int ch=0; ch<8; ch++) {
            int kc = ch*32;
#pragma unroll
            for (int l=0;l<2;l++) {
                int idx = tid + l*256;
                int row = idx>>3, q = (idx&7)*4;
                float4 v = *(const float4*)(x + (size_t)(tok0+row)*CC + kc + q);
                Xpk[q>>1][row]     = pk2(v.x, v.y);
                Xpk[(q>>1)+1][row] = pk2(v.z, v.w);
            }
            {
                int row = tid>>2, q = (tid&3)*8;   // 64 rows x 32k via 2 float4 per thread
                float4 v = *(const float4*)(src + (size_t)row*CC + kc + q);
                Mpk[q>>1][row]     = pk2(v.x, v.y);
                Mpk[(q>>1)+1][row] = pk2(v.z, v.w);
                float4 w = *(const float4*)(src + (size_t)row*CC + kc + q + 4);
                Mpk[(q>>1)+2][row] = pk2(w.x, w.y);
                Mpk[(q>>1)+3][row] = pk2(w.z, w.w);
            }
            __syncthreads();
#pragma unroll
            for (int kpb=0; kpb<16; kpb+=8) {
                uint32_t a[2][4], bv[2][2];
#pragma unroll
                for (int mt=0;mt<2;mt++) {
                    int m0 = wm*32 + mt*16 + gid;
                    a[mt][0]=Xpk[kpb+tig][m0];
                    a[mt][1]=Xpk[kpb+tig][m0+8];
                    a[mt][2]=Xpk[kpb+tig+4][m0];
                    a[mt][3]=Xpk[kpb+tig+4][m0+8];
                }
#pragma unroll
                for (int nt=0;nt<2;nt++) {
                    int nl = wn*16 + nt*8 + gid;
                    bv[nt][0]=Mpk[kpb+tig][nl];
                    bv[nt][1]=Mpk[kpb+tig+4][nl];
                }
#pragma unroll
                for (int mt=0;mt<2;mt++)
#pragma unroll
                    for (int nt=0;nt<2;nt++) mma16bf(acc[mt][nt], a[mt], bv[nt]);
            }
            __syncthreads();
        }
        float s0 = 0.f;
#pragma unroll
        for (int mt=0;mt<2;mt++)
#pragma unroll
            for (int nt=0;nt<2;nt++) {
                int col = colgrp*64 + wn*16 + nt*8 + 2*tig;
#pragma unroll
                for (int rr=0;rr<2;rr++) {
                    int tok = tok0 + wm*32 + mt*16 + gid + rr*8;
                    s0 += acc[mt][nt][rr*2]   * x[(size_t)tok*CC + col];
                    s0 += acc[mt][nt][rr*2+1] * x[(size_t)tok*CC + col+1];
                }
            }
        red[tid] = s0; __syncthreads();
        for (int s=128;s>=1;s>>=1) { if (tid<s) red[tid]+=red[tid+s]; __syncthreads(); }
        if (tid == 0) atomicAdd(&g_accd[0], (double)red[0]);
        return;
    }
    // ---- mode 1: xG = X@G^T, tf32 hi/lo (routing-critical), + softmax/S1a/binning ----
    float (*Xs)[36] = (float (*)[36])smp;
    float (*Bs)[36] = (float (*)[36])(smp + 9216);
    float (*xgs)[68] = (float (*)[68])(smp + 18432);
    int tok0 = (b-128)*64;
    float acc[2][2][4];
#pragma unroll
    for (int mt=0;mt<2;mt++)
#pragma unroll
        for (int nt=0;nt<2;nt++)
#pragma unroll
            for (int q=0;q<4;q++) acc[mt][nt][q]=0.f;

    for (int ch=0; ch<8; ch++) {
        int kc = ch*32;
#pragma unroll
        for (int l=0;l<2;l++) {
            int idx = tid + l*256;
            int row = idx>>3, q = (idx&7)*4;
            float4 v = *(const float4*)(x + (size_t)(tok0+row)*CC + kc + q);
            Xs[row][q]=v.x; Xs[row][q+1]=v.y; Xs[row][q+2]=v.z; Xs[row][q+3]=v.w;
            float4 w = *(const float4*)(g_G + (size_t)row*CC + kc + q);
            Bs[row][q]=w.x; Bs[row][q+1]=w.y; Bs[row][q+2]=w.z; Bs[row][q+3]=w.w;
        }
        __syncthreads();
#pragma unroll
        for (int k8=0;k8<4;k8++) {
            int kb = k8*8;
            uint32_t ah[2][4], al[2][4], bh[2][2], bl[2][2];
#pragma unroll
            for (int mt=0;mt<2;mt++) {
                int m0 = wm*32 + mt*16 + gid;
                hilo(Xs[m0][kb+tig],     ah[mt][0], al[mt][0]);
                hilo(Xs[m0+8][kb+tig],   ah[mt][1], al[mt][1]);
                hilo(Xs[m0][kb+tig+4],   ah[mt][2], al[mt][2]);
                hilo(Xs[m0+8][kb+tig+4], ah[mt][3], al[mt][3]);
            }
#pragma unroll
            for (int nt=0;nt<2;nt++) {
                int nl = wn*16 + nt*8 + gid;
                hilo(Bs[nl][kb+tig],   bh[nt][0], bl[nt][0]);
                hilo(Bs[nl][kb+tig+4], bh[nt][1], bl[nt][1]);
            }
#pragma unroll
            for (int mt=0;mt<2;mt++)
#pragma unroll
                for (int nt=0;nt<2;nt++) {
                    mma8(acc[mt][nt], ah[mt], bh[nt]);
                    mma8(acc[mt][nt], ah[mt], bl[nt]);
                    mma8(acc[mt][nt], al[mt], bh[nt]);
                }
        }
        __syncthreads();
    }
#pragma unroll
    for (int mt=0;mt<2;mt++)
#pragma unroll
        for (int nt=0;nt<2;nt++) {
            int col = wn*16 + nt*8 + 2*tig;
#pragma unroll
            for (int rr=0;rr<2;rr++) {
                int lt = wm*32 + mt*16 + gid + rr*8;
                xgs[lt][col]   = acc[mt][nt][rr*2];
                xgs[lt][col+1] = acc[mt][nt][rr*2+1];
            }
        }
    __syncthreads();
    float cn0 = (float)g_cnormd[lane], cn1 = (float)g_cnormd[lane+32];
    float bc0 = (float)g_bcd[lane],    bc1 = (float)g_bcd[lane+32];
    float s1acc = 0.f;
    for (int k=0;k<8;k++) {
        int lt = warp*8 + k;
        size_t n = tok0 + lt;
        float xg0 = xgs[lt][lane]    + bc0;
        float xg1 = xgs[lt][lane+32] + bc1;
        float l0 = 2.f*xg0 - cn0 - logf(-logf(u[n*NE+lane]));
        float l1 = 2.f*xg1 - cn1 - logf(-logf(u[n*NE+lane+32]));
        float m = fmaxf(l0, l1);
#pragma unroll
        for (int o=16;o>=1;o>>=1) m = fmaxf(m, __shfl_xor_sync(0xffffffffu, m, o));
        float ex0 = expf(l0 - m), ex1 = expf(l1 - m);
        float S = ex0 + ex1;
#pragma unroll
        for (int o=16;o>=1;o>>=1) S += __shfl_xor_sync(0xffffffffu, S, o);
        float r0 = ex0 / S, r1 = ex1 / S;
        g_resp[n*NE+lane]    = r0;
        g_resp[n*NE+lane+32] = r1;
        float s1 = r0*xg0 + r1*xg1;
#pragma unroll
        for (int o=16;o>=1;o>>=1) s1 += __shfl_xor_sync(0xffffffffu, s1, o);
        if (lane == 0) s1acc += s1;
        if (r0 > 1e-9f) {
            int p = atomicAdd(&g_cnt[lane], 1);
            g_tokn[lane*NN+p] = (int)n; g_tokr[lane*NN+p] = r0;
        }
        if (r1 > 1e-9f) {
            int p = atomicAdd(&g_cnt[lane+32], 1);
            g_tokn[(lane+32)*NN+p] = (int)n; g_tokr[(lane+32)*NN+p] = r1;
        }
    }
    if (lane == 0) atomicAdd(&g_accd[1], (double)s1acc);
}

// ================= A=R^T X (plain), Q=R^T R (hi/lo), s, xsum  (32 tokens/blk) =================
__global__ void __launch_bounds__(256) k_RX(const float* __restrict__ x) {
    __shared__ float Rs[32][68];
    __shared__ float Xs[32][260];
    int tid=threadIdx.x, warp=tid>>5, lane=tid&31, gid=lane>>2, tig=lane&3;
    int nb = blockIdx.x * 32;
    float accA[4][4][4], accQ[4][4];
#pragma unroll
    for (int mt=0;mt<4;mt++) {
#pragma unroll
        for (int nt=0;nt<4;nt++)
#pragma unroll
            for (int q=0;q<4;q++) accA[mt][nt][q]=0.f;
#pragma unroll
        for (int q=0;q<4;q++) accQ[mt][q]=0.f;
    }
    float sp=0.f, xsacc=0.f;

#pragma unroll
    for (int l=0;l<8;l++) {
        int idx = tid + l*256;
        int row = idx>>6, e2 = idx&63;
        Rs[row][e2] = g_resp[(size_t)(nb+row)*NE + e2];
    }
#pragma unroll
    for (int l=0;l<8;l++) {
        int idx = tid + l*256;
        int row = idx>>6, q = (idx&63)*4;
        float4 v = *(const float4*)(x + (size_t)(nb+row)*CC + q);
        Xs[row][q]=v.x; Xs[row][q+1]=v.y; Xs[row][q+2]=v.z; Xs[row][q+3]=v.w;
    }
    __syncthreads();
    if (tid < 64) {
        for (int k=0;k<32;k++) sp += Rs[k][tid];
    }
    for (int k=0;k<32;k++) xsacc += Xs[k][tid];
#pragma unroll
    for (int k8=0;k8<4;k8++) {
        int kb = k8*8;
        uint32_t am[4][4], amh[4][4], aml[4][4];
#pragma unroll
        for (int mt=0;mt<4;mt++) {
            int m0 = mt*16;
            float v0 = Rs[kb+tig][m0+gid],   v1 = Rs[kb+tig][m0+gid+8];
            float v2 = Rs[kb+tig+4][m0+gid], v3 = Rs[kb+tig+4][m0+gid+8];
            am[mt][0]=fb(v0); am[mt][1]=fb(v1); am[mt][2]=fb(v2); am[mt][3]=fb(v3);
            hilo(v0, amh[mt][0], aml[mt][0]); hilo(v1, amh[mt][1], aml[mt][1]);
            hilo(v2, amh[mt][2], aml[mt][2]); hilo(v3, amh[mt][3], aml[mt][3]);
        }
#pragma unroll
        for (int nt=0;nt<4;nt++) {
            int c = warp*32 + nt*8 + gid;
            uint32_t bx[2] = { fb(Xs[kb+tig][c]), fb(Xs[kb+tig+4][c]) };
#pragma unroll
            for (int mt=0;mt<4;mt++) mma8(accA[mt][nt], am[mt], bx);
        }
        {
            int eq = warp*8 + gid;
            uint32_t bqh[2], bql[2];
            hilo(Rs[kb+tig][eq],   bqh[0], bql[0]);
            hilo(Rs[kb+tig+4][eq], bqh[1], bql[1]);
#pragma unroll
            for (int mt=0;mt<4;mt++) {
                mma8(accQ[mt], amh[mt], bqh);
                mma8(accQ[mt], amh[mt], bql);
                mma8(accQ[mt], aml[mt], bqh);
            }
        }
    }
#pragma unroll
    for (int mt=0;mt<4;mt++) {
#pragma unroll
        for (int nt=0;nt<4;nt++) {
            int e = mt*16 + gid;
            int c = warp*32 + nt*8 + 2*tig;
            atomicAdd(&g_A[e*CC+c],        accA[mt][nt][0]);
            atomicAdd(&g_A[e*CC+c+1],      accA[mt][nt][1]);
            atomicAdd(&g_A[(e+8)*CC+c],    accA[mt][nt][2]);
            atomicAdd(&g_A[(e+8)*CC+c+1],  accA[mt][nt][3]);
        }
        int e = mt*16 + gid;
        int eq = warp*8 + 2*tig;
        atomicAdd(&g_Q[e*NE+eq],       accQ[mt][0]);
        atomicAdd(&g_Q[e*NE+eq+1],     accQ[mt][1]);
        atomicAdd(&g_Q[(e+8)*NE+eq],   accQ[mt][2]);
        atomicAdd(&g_Q[(e+8)*NE+eq+1], accQ[mt][3]);
    }
    if (tid < 64) atomicAdd(&g_s[tid], sp);
    atomicAdd(&g_xsum[tid], xsacc);
}

// ================= Cnew bf16 (512 blks) | loss contractions (64 blks) =================
__global__ void __launch_bounds__(256) k_cnew(const float* __restrict__ W,
                                              const float* __restrict__ cents,
                                              const float* __restrict__ bvec) {
    int tid=threadIdx.x, warp=tid>>5, lane=tid&31, gid=lane>>2, tig=lane&3;
    if (blockIdx.x >= 512) {
        int e = blockIdx.x - 512;
        __shared__ float As[256];
        __shared__ float red[256];
        As[tid] = g_A[e*CC + tid];
        __syncthreads();
        float uv = 0.f;
        for (int e2=0;e2<NE;e2++) uv += g_Q[e*NE+e2] * g_A[e2*CC + tid];
        float am = 0.f;
        for (int c=0;c<CC;c++) am += As[c] * g_M[c*CC + tid];
        float a = As[tid];
        float ge = g_G[e*CC + tid];
        float wtb = g_Wtb[tid];

        float r1, r2, r3, r4, r5, r6;
        red[tid] = am*a; __syncthreads();
        for (int s=128;s>=1;s>>=1) { if (tid<s) red[tid]+=red[tid+s]; __syncthreads(); }
        r1 = red[0]; __syncthreads();
        red[tid] = a*wtb; __syncthreads();
        for (int s=128;s>=1;s>>=1) { if (tid<s) red[tid]+=red[tid+s]; __syncthreads(); }
        r2 = red[0]; __syncthreads();
        red[tid] = ge*uv; __syncthreads();
        for (int s=128;s>=1;s>>=1) { if (tid<s) red[tid]+=red[tid+s]; __syncthreads(); }
        r3 = red[0]; __syncthreads();
        red[tid] = am*uv; __syncthreads();
        for (int s=128;s>=1;s>>=1) { if (tid<s) red[tid]+=red[tid+s]; __syncthreads(); }
        r4 = red[0]; __syncthreads();
        red[tid] = (tid < NE) ? g_Q[e*NE+tid]*g_s[tid] : 0.f; __syncthreads();
        for (int s=128;s>=1;s>>=1) { if (tid<s) red[tid]+=red[tid+s]; __syncthreads(); }
        r5 = red[0]; __syncthreads();
        red[tid] = (tid < NE) ? g_CG[e*NE+tid]*g_Q[e*NE+tid] : 0.f; __syncthreads();
        for (int s=128;s>=1;s>>=1) { if (tid<s) red[tid]+=red[tid+s]; __syncthreads(); }
        r6 = red[0]; __syncthreads();

        if (tid == 0) {
            double se = (double)g_s[e];
            double bb = g_bbd;
            double bce = g_bcd[e];
            double d = 0.999, gam = (double)GAMv;
            double p_e = (double)r1 + 2.0*se*(double)r2 + bb*se*se;
            double quad_e = d*d*(double)r6
                          + 2.0*d*gam*((double)r3 + bce*(double)r5)
                          + gam*gam*((double)r4 + 2.0*(double)r2*(double)r5 + bb*se*(double)r5);
            atomicAdd(&g_accd[2], p_e);
            atomicAdd(&g_accd[3], quad_e);
        }
        if (e == 0) {
            red[tid] = 2.f*g_xsum[tid]*g_Wtb[tid]; __syncthreads();
            for (int s=128;s>=1;s>>=1) { if (tid<s) red[tid]+=red[tid+s]; __syncthreads(); }
            if (tid == 0) atomicAdd(&g_accd[0], (double)red[0] + (double)NN * g_bbd);
        }
        return;
    }
    // ---- Cnew = decay*Cents + gam*(A@W^T + s b^T), bf16 m16n8k16 ----
    __shared__ uint32_t Apk[16][68];
    __shared__ uint32_t Wpk[16][132];
    __shared__ float ss[64];
    int d0 = blockIdx.x * 128;
    if (tid < 64) ss[tid] = g_s[tid];
    float acc[4][2][4];
#pragma unroll
    for (int mt=0;mt<4;mt++)
#pragma unroll
        for (int nt=0;nt<2;nt++)
#pragma unroll
            for (int q=0;q<4;q++) acc[mt][nt][q]=0.f;

    for (int ch=0; ch<8; ch++) {
        int kc = ch*32;
#pragma unroll
        for (int l=0;l<2;l++) {
            int idx = tid + l*256;
            int e = idx>>3, q = (idx&7)*4;
            float4 v = *(const float4*)(g_A + (size_t)e*CC + kc + q);
            Apk[q>>1][e]     = pk2(v.x, v.y);
            Apk[(q>>1)+1][e] = pk2(v.z, v.w);
        }
#pragma unroll
        for (int l=0;l<4;l++) {
            int idx = tid + l*256;
            int row = idx>>3, q = (idx&7)*4;
            float4 v = *(const float4*)(W + (size_t)(d0+row)*CC + kc + q);
            Wpk[q>>1][row]     = pk2(v.x, v.y);
            Wpk[(q>>1)+1][row] = pk2(v.z, v.w);
        }
        __syncthreads();
#pragma unroll
        for (int kpb=0; kpb<16; kpb+=8) {
            uint32_t a[4][4], b[2][2];
#pragma unroll
            for (int mt=0;mt<4;mt++) {
                int e = mt*16 + gid;
                a[mt][0]=Apk[kpb+tig][e];
                a[mt][1]=Apk[kpb+tig][e+8];
                a[mt][2]=Apk[kpb+tig+4][e];
                a[mt][3]=Apk[kpb+tig+4][e+8];
            }
#pragma unroll
            for (int nt=0;nt<2;nt++) {
                int dl = warp*16 + nt*8 + gid;
                b[nt][0]=Wpk[kpb+tig][dl];
                b[nt][1]=Wpk[kpb+tig+4][dl];
            }
#pragma unroll
            for (int mt=0;mt<4;mt++)
#pragma unroll
                for (int nt=0;nt<2;nt++) mma16bf(acc[mt][nt], a[mt], b[nt]);
        }
        __syncthreads();
    }
#pragma unroll
    for (int mt=0;mt<4;mt++)
#pragma unroll
        for (int nt=0;nt<2;nt++) {
            int e = mt*16 + gid;
            int d = d0 + warp*16 + nt*8 + 2*tig;
            float b0 = bvec[d], b1 = bvec[d+1];
            g_Cnew[(size_t)e*DD+d]       = DECAYv*cents[(size_t)e*DD+d]       + GAMv*(acc[mt][nt][0] + ss[e]*b0);
            g_Cnew[(size_t)e*DD+d+1]     = DECAYv*cents[(size_t)e*DD+d+1]     + GAMv*(acc[mt][nt][1] + ss[e]*b1);
            g_Cnew[(size_t)(e+8)*DD+d]   = DECAYv*cents[(size_t)(e+8)*DD+d]   + GAMv*(acc[mt][nt][2] + ss[e+8]*b0);
            g_Cnew[(size_t)(e+8)*DD+d+1] = DECAYv*cents[(size_t)(e+8)*DD+d+1] + GAMv*(acc[mt][nt][3] + ss[e+8]*b1);
        }
}

// ================= binned output GEMM (bf16 hi/lo), persistent 8 slots/expert =================
__global__ void __launch_bounds__(256) k_out(float* __restrict__ out) {
    __shared__ __align__(16) char smp[70400];
    int b = blockIdx.x;
    int tid=threadIdx.x, warp=tid>>5, lane=tid&31, gid=lane>>2, tig=lane&3;
    int e = b & 63;
    int cnt = g_cnt[e];
    float (*ys)[260] = (float (*)[260])smp;
    float (*Cw)[36]  = (float (*)[36])(smp + 33280);
    int* stok        = (int*)(smp + 33280 + 36864);
    int wm = warp>>2, wn = warp&3;

    for (int a0 = (b >> 6) * 32; a0 < cnt; a0 += 256) {
#pragma unroll
        for (int l=0;l<8;l++) {
            int idx = tid + l*256;
            int row = idx >> 6, q = idx & 63;
            int aa = a0 + row;
            float r = 0.f; int n = 0;
            float4 v = make_float4(0.f,0.f,0.f,0.f);
            if (aa < cnt) {
                n = g_tokn[e*NN+aa]; r = g_tokr[e*NN+aa];
                v = *(const float4*)(g_Y + (size_t)n*CC + q*4);
            }
            ys[row][q*4]=r*v.x; ys[row][q*4+1]=r*v.y; ys[row][q*4+2]=r*v.z; ys[row][q*4+3]=r*v.w;
            if (q == 0) stok[row] = n;
        }
        __syncthreads();
        float acc[8][4];
#pragma unroll
        for (int nt=0;nt<8;nt++)
#pragma unroll
            for (int q=0;q<4;q++) acc[nt][q]=0.f;

        for (int ch=0; ch<8; ch++) {
            int kc = ch*32;
#pragma unroll
            for (int l=0;l<8;l++) {
                int idx = tid + l*256;
                int row = idx >> 3, q = (idx & 7)*4;
                float4 v = *(const float4*)(g_Cnew + (size_t)e*DD + (size_t)row*CC + kc + q);
                Cw[row][q]=v.x; Cw[row][q+1]=v.y; Cw[row][q+2]=v.z; Cw[row][q+3]=v.w;
            }
            __syncthreads();
#pragma unroll
            for (int kpb=0; kpb<16; kpb+=8) {
                uint32_t ah[4], al[4];
                int m0 = wm*16 + gid;
                int k0 = 2*(kpb+tig), k1 = 2*(kpb+tig+4);
                pkhl(ys[m0][kc+k0],   ys[m0][kc+k0+1],   ah[0], al[0]);
                pkhl(ys[m0+8][kc+k0], ys[m0+8][kc+k0+1], ah[1], al[1]);
                pkhl(ys[m0][kc+k1],   ys[m0][kc+k1+1],   ah[2], al[2]);
                pkhl(ys[m0+8][kc+k1], ys[m0+8][kc+k1+1], ah[3], al[3]);
#pragma unroll
                for (int nt=0;nt<8;nt++) {
                    int nc = wn*64 + nt*8 + gid;
                    uint32_t bh[2], bl[2];
                    pkhl(Cw[nc][k0], Cw[nc][k0+1], bh[0], bl[0]);
                    pkhl(Cw[nc][k1], Cw[nc][k1+1], bh[1], bl[1]);
                    mma16bf(acc[nt], ah, bh);
                    mma16bf(acc[nt], ah, bl);
                    mma16bf(acc[nt], al, bh);
                }
            }
            __syncthreads();
        }
        int t0 = wm*16 + gid;
        int r0 = stok[t0], r1 = stok[t0+8];
#pragma unroll
        for (int nt=0;nt<8;nt++) {
            int i = wn*64 + nt*8 + 2*tig;
            atomicAdd(out + (size_t)r0*ROUT + i,   acc[nt][0]);
            atomicAdd(out + (size_t)r0*ROUT + i+1, acc[nt][1]);
            atomicAdd(out + (size_t)r1*ROUT + i,   acc[nt][2]);
            atomicAdd(out + (size_t)r1*ROUT + i+1, acc[nt][3]);
        }
        __syncthreads();
    }
}

// ================= final: bias | loss scalar =================
__global__ void k_fin(float* __restrict__ out, const float* __restrict__ pwB, int out_size) {
    int b = blockIdx.x, tid = threadIdx.x;
    if (b < NN) {
        out[(size_t)b*ROUT + tid] += pwB[tid];
        return;
    }
    double S1 = 0.999*g_accd[1] + (double)GAMv*g_accd[2];
    double loss = 0.25*(g_accd[0] - 2.0*S1 + g_accd[3]) / ((double)NN * (double)DD);
    float lf = (float)loss;
    for (int i = NN*ROUT + tid; i < out_size; i += 256) out[i] = lf;
}

extern "C" void kernel_launch(void* const* d_in, const int* in_sizes, int n_in,
                              void* d_out, int out_size) {
    const float* x     = (const float*)d_in[0];
    const float* u     = (const float*)d_in[1];
    const float* W     = (const float*)d_in[2];
    const float* bvec  = (const float*)d_in[3];
    const float* pw1   = (const float*)d_in[4];
    const float* pwB   = (const float*)d_in[5];
    const float* cents = (const float*)d_in[6];
    float* out = (float*)d_out;

    k_zero<<<2048, 256>>>(out);
    k_p1<<<512, 256>>>(W, cents, bvec, x, pw1);
    k_big2<<<160, 256>>>(x, u);
    k_RX<<<64, 256>>>(x);
    k_cnew<<<576, 256>>>(W, cents, bvec);
    k_out<<<512, 256>>>(out);
    k_fin<<<NN + 1, 256>>>(out, pwB, out_size);
}

// round 14
// speedup vs baseline: 1.1560x; 1.0319x over previous
#include <cuda_runtime.h>
#include <cuda_bf16.h>
#include <math.h>
#include <stdint.h>

#define CC 256
#define NN 2048
#define DD 65536
#define NE 64
#define ROUT 256
#define DECAYv 0.999f
#define GAMv 4.8828125e-7f
#define COMMITv 0.25f

__device__ float g_M[CC*CC];
__device__ float g_G[NE*CC];
__device__ float g_A[NE*CC];
__device__ float g_Q[NE*NE];
__device__ float g_CG[NE*NE];
__device__ double g_cnormd[NE], g_bcd[NE], g_bbd;
__device__ float g_s[NE];
__device__ float g_Wtb[CC];
__device__ float g_xsum[CC];
__device__ double g_accd[4];      // 0:S0  1:S1a  2:p  3:quad
__device__ float g_Y[NN*CC];
__device__ float g_resp[NN*NE];
__device__ int   g_cnt[NE];
__device__ int   g_tokn[NE*NN];
__device__ float g_tokr[NE*NN];
__device__ float g_Cnew[NE*DD];

__device__ __forceinline__ void mma8(float* c, const uint32_t* a, const uint32_t* b) {
    asm volatile("mma.sync.aligned.m16n8k8.row.col.f32.tf32.tf32.f32 "
        "{%0,%1,%2,%3}, {%4,%5,%6,%7}, {%8,%9}, {%0,%1,%2,%3};"
        : "+f"(c[0]), "+f"(c[1]), "+f"(c[2]), "+f"(c[3])
        : "r"(a[0]), "r"(a[1]), "r"(a[2]), "r"(a[3]), "r"(b[0]), "r"(b[1]));
}
__device__ __forceinline__ void mma16bf(float* c, const uint32_t* a, const uint32_t* b) {
    asm volatile("mma.sync.aligned.m16n8k16.row.col.f32.bf16.bf16.f32 "
        "{%0,%1,%2,%3}, {%4,%5,%6,%7}, {%8,%9}, {%0,%1,%2,%3};"
        : "+f"(c[0]), "+f"(c[1]), "+f"(c[2]), "+f"(c[3])
        : "r"(a[0]), "r"(a[1]), "r"(a[2]), "r"(a[3]), "r"(b[0]), "r"(b[1]));
}
__device__ __forceinline__ uint32_t fb(float x) { return __float_as_uint(x); }
__device__ __forceinline__ uint32_t pk2(float a, float b) {
    __nv_bfloat162 p = __floats2bfloat162_rn(a, b);
    return *(uint32_t*)&p;
}
__device__ __forceinline__ void pkhl(float v0, float v1, uint32_t& h, uint32_t& l) {
    __nv_bfloat16 h0 = __float2bfloat16(v0);
    __nv_bfloat16 h1 = __float2bfloat16(v1);
    float l0 = v0 - __bfloat162float(h0);
    float l1 = v1 - __bfloat162float(h1);
    __nv_bfloat162 hh; hh.x = h0; hh.y = h1;
    h = *(uint32_t*)&hh;
    l = pk2(l0, l1);
}
__device__ __forceinline__ void hilo(float v, uint32_t& h, uint32_t& l) {
    uint32_t hb = __float_as_uint(v) & 0xFFFFE000u;
    h = hb;
    l = fb(v - __uint_as_float(hb));
}
__device__ __forceinline__ float upk_sum(uint32_t h, uint32_t l, int half) {
    __nv_bfloat162 hh = *(__nv_bfloat162*)&h;
    __nv_bfloat162 ll = *(__nv_bfloat162*)&l;
    return half ? (__bfloat162float(hh.y) + __bfloat162float(ll.y))
                : (__bfloat162float(hh.x) + __bfloat162float(ll.x));
}

// ================= zero =================
__global__ void k_zero(float* __restrict__ out) {
    int i = blockIdx.x * 256 + threadIdx.x;
    if (i < NN*ROUT) out[i] = 0.f;
    if (i < CC*CC) g_M[i] = 0.f;
    if (i < NE*CC) { g_G[i]=0.f; g_A[i]=0.f; }
    if (i < NE*NE) { g_Q[i]=0.f; g_CG[i]=0.f; }
    if (i < CC) { g_Wtb[i] = 0.f; g_xsum[i] = 0.f; }
    if (i < NE) { g_cnormd[i]=0.0; g_bcd[i]=0.0; g_s[i]=0.f; g_cnt[i]=0; }
    if (i < 4) g_accd[i] = 0.0;
    if (i == 4) g_bbd = 0.0;
}

// ================= phase 1: gram(M bf16,128) | centW(G bf16-hilo + CG bf16, 256) | Y(bf16-hilo,128) =================
__global__ void __launch_bounds__(256) k_p1(const float* __restrict__ W,
                                            const float* __restrict__ cents,
                                            const float* __restrict__ bvec,
                                            const float* __restrict__ x,
                                            const float* __restrict__ pw1) {
    __shared__ __align__(16) char smp[51456];
    int b = blockIdx.x;
    int tid=threadIdx.x, warp=tid>>5, lane=tid&31, gid=lane>>2, tig=lane&3;

    if (b < 128) {
        // ---- gram: M = W^T W in bf16 m16n8k16 (loss-only path) ----
        uint32_t (*Wp)[260] = (uint32_t (*)[260])smp;
        int wm = warp>>2, wn = warp&3;
        int i0 = (b & 1) * 128;
        int d0 = (b >> 1) * 1024;
        float acc[4][8][4];
#pragma unroll
        for (int mt=0;mt<4;mt++)
#pragma unroll
            for (int nt=0;nt<8;nt++)
#pragma unroll
                for (int q=0;q<4;q++) acc[mt][nt][q]=0.f;

        for (int ch=0; ch<32; ch++) {
            int drow = d0 + ch*32;
#pragma unroll
            for (int l=0;l<16;l++) {
                int idx = tid + l*256;
                int kp = idx >> 8, c = idx & 255;
                float v0 = W[(size_t)(drow + 2*kp)   * CC + c];
                float v1 = W[(size_t)(drow + 2*kp+1) * CC + c];
                Wp[kp][c] = pk2(v0, v1);
            }
            __syncthreads();
#pragma unroll
            for (int st=0; st<2; st++) {
                int kpb = st*8;
                uint32_t a[4][4];
#pragma unroll
                for (int mt=0;mt<4;mt++) {
                    int ib = i0 + wm*64 + mt*16 + gid;
                    a[mt][0]=Wp[kpb+tig][ib];
                    a[mt][1]=Wp[kpb+tig][ib+8];
                    a[mt][2]=Wp[kpb+tig+4][ib];
                    a[mt][3]=Wp[kpb+tig+4][ib+8];
                }
#pragma unroll
                for (int nt=0;nt<8;nt++) {
                    int jb = wn*64 + nt*8 + gid;
                    uint32_t bv[2] = { Wp[kpb+tig][jb], Wp[kpb+tig+4][jb] };
#pragma unroll
                    for (int mt=0;mt<4;mt++) mma16bf(acc[mt][nt], a[mt], bv);
                }
            }
            __syncthreads();
        }
#pragma unroll
        for (int mt=0;mt<4;mt++)
#pragma unroll
            for (int nt=0;nt<8;nt++) {
                int i = i0 + wm*64 + mt*16 + gid;
                int j = wn*64 + nt*8 + 2*tig;
                atomicAdd(&g_M[i*CC+j],       acc[mt][nt][0]);
                atomicAdd(&g_M[i*CC+j+1],     acc[mt][nt][1]);
                atomicAdd(&g_M[(i+8)*CC+j],   acc[mt][nt][2]);
                atomicAdd(&g_M[(i+8)*CC+j+1], acc[mt][nt][3]);
            }
    } else if (b < 384) {
        // ---- centW: G bf16-hilo (routing) + CG bf16-hi (loss) + cnorm/bc/Wtb/bb ----
        float (*Cs)[36]      = (float (*)[36])smp;                  // 9216
        uint32_t (*Cph)[68]  = (uint32_t (*)[68])(smp + 9216);      // 4352
        uint32_t (*Cpl)[68]  = (uint32_t (*)[68])(smp + 13568);     // 4352
        uint32_t (*Wph)[260] = (uint32_t (*)[260])(smp + 17920);    // 16640
        uint32_t (*Wpl)[260] = (uint32_t (*)[260])(smp + 34560);    // 16640
        float* bs            = (float*)(smp + 51200);               // 128
        int blk = b - 128;
        int d0 = blk * 256;
        float accG[4][4][4], accCG[4][4];
#pragma unroll
        for (int mt=0;mt<4;mt++) {
#pragma unroll
            for (int nt=0;nt<4;nt++)
#pragma unroll
                for (int q=0;q<4;q++) accG[mt][nt][q]=0.f;
#pragma unroll
            for (int q=0;q<4;q++) accCG[mt][q]=0.f;
        }
        float accWtb=0.f, accCN=0.f, accBC=0.f, accBB=0.f;

        for (int ch=0; ch<8; ch++) {
            int dbase = d0 + ch*32;
#pragma unroll
            for (int l=0;l<2;l++) {
                int idx = tid + l*256;
                int e = idx>>3, q = (idx&7)*4;
                float4 v = *(const float4*)(cents + (size_t)e*DD + dbase + q);
                Cs[e][q]=v.x; Cs[e][q+1]=v.y; Cs[e][q+2]=v.z; Cs[e][q+3]=v.w;
                pkhl(v.x, v.y, Cph[q>>1][e],     Cpl[q>>1][e]);
                pkhl(v.z, v.w, Cph[(q>>1)+1][e], Cpl[(q>>1)+1][e]);
            }
#pragma unroll
            for (int l=0;l<16;l++) {
                int idx = tid + l*256;
                int kp = idx >> 8, c = idx & 255;
                float v0 = W[(size_t)(dbase + 2*kp)   * CC + c];
                float v1 = W[(size_t)(dbase + 2*kp+1) * CC + c];
                pkhl(v0, v1, Wph[kp][c], Wpl[kp][c]);
            }
            if (tid < 32) bs[tid] = bvec[dbase + tid];
            __syncthreads();
            {
                float aw = 0.f;
#pragma unroll
                for (int kp=0;kp<16;kp++) {
                    aw += bs[2*kp]   * upk_sum(Wph[kp][tid], Wpl[kp][tid], 0);
                    aw += bs[2*kp+1] * upk_sum(Wph[kp][tid], Wpl[kp][tid], 1);
                }
                accWtb += aw;
            }
            if (tid < 64) {
                float cn=0.f, bc=0.f;
                for (int k=0;k<32;k++) { float c=Cs[tid][k]; cn+=c*c; bc+=c*bs[k]; }
                accCN += cn; accBC += bc;
            }
            if (tid == 64) {
                float sb=0.f;
                for (int k=0;k<32;k++) sb += bs[k]*bs[k];
                accBB += sb;
            }
            // G: bf16 hi/lo (3x mma16) — routing precision ~2^-17/elem
#pragma unroll
            for (int kpb=0; kpb<16; kpb+=8) {
                uint32_t ah[4][4], al[4][4];
#pragma unroll
                for (int mt=0;mt<4;mt++) {
                    int e = mt*16 + gid;
                    ah[mt][0]=Cph[kpb+tig][e];   al[mt][0]=Cpl[kpb+tig][e];
                    ah[mt][1]=Cph[kpb+tig][e+8]; al[mt][1]=Cpl[kpb+tig][e+8];
                    ah[mt][2]=Cph[kpb+tig+4][e];   al[mt][2]=Cpl[kpb+tig+4][e];
                    ah[mt][3]=Cph[kpb+tig+4][e+8]; al[mt][3]=Cpl[kpb+tig+4][e+8];
                }
#pragma unroll
                for (int nt=0;nt<4;nt++) {
                    int c = warp*32 + nt*8 + gid;
                    uint32_t bh[2] = { Wph[kpb+tig][c], Wph[kpb+tig+4][c] };
                    uint32_t bl[2] = { Wpl[kpb+tig][c], Wpl[kpb+tig+4][c] };
#pragma unroll
                    for (int mt=0;mt<4;mt++) {
                        mma16bf(accG[mt][nt], ah[mt], bh);
                        mma16bf(accG[mt][nt], ah[mt], bl);
                        mma16bf(accG[mt][nt], al[mt], bh);
                    }
                }
                // CG: bf16-hi only (loss)
                {
                    int n0q = warp*8 + gid;
                    uint32_t bcg[2] = { Cph[kpb+tig][n0q], Cph[kpb+tig+4][n0q] };
#pragma unroll
                    for (int mt=0;mt<4;mt++) mma16bf(accCG[mt], ah[mt], bcg);
                }
            }
            __syncthreads();
        }
#pragma unroll
        for (int mt=0;mt<4;mt++) {
#pragma unroll
            for (int nt=0;nt<4;nt++) {
                int e = mt*16 + gid;
                int c = warp*32 + nt*8 + 2*tig;
                atomicAdd(&g_G[e*CC+c],       accG[mt][nt][0]);
                atomicAdd(&g_G[e*CC+c+1],     accG[mt][nt][1]);
                atomicAdd(&g_G[(e+8)*CC+c],   accG[mt][nt][2]);
                atomicAdd(&g_G[(e+8)*CC+c+1], accG[mt][nt][3]);
            }
            int e = mt*16 + gid;
            int n = warp*8 + 2*tig;
            atomicAdd(&g_CG[e*NE+n],       accCG[mt][0]);
            atomicAdd(&g_CG[e*NE+n+1],     accCG[mt][1]);
            atomicAdd(&g_CG[(e+8)*NE+n],   accCG[mt][2]);
            atomicAdd(&g_CG[(e+8)*NE+n+1], accCG[mt][3]);
        }
        atomicAdd(&g_Wtb[tid], accWtb);
        if (tid < 64) { atomicAdd(&g_cnormd[tid], (double)accCN); atomicAdd(&g_bcd[tid], (double)accBC); }
        if (tid == 64) atomicAdd(&g_bbd, (double)accBB);
    } else {
        // ---- Y = X @ pw1^T  (bf16 hi/lo, output-precision) ----
        float (*Xs)[36] = (float (*)[36])smp;
        float (*Bs)[36] = (float (*)[36])(smp + 9216);
        int yb = b - 384;
        int tok0 = (yb >> 2) * 64;
        int colgrp = yb & 3;
        const float* src = pw1 + (size_t)colgrp * 64 * CC;
        int wm = warp>>2, wn = warp&3;
        float acc[2][2][4];
#pragma unroll
        for (int mt=0;mt<2;mt++)
#pragma unroll
            for (int nt=0;nt<2;nt++)
#pragma unroll
                for (int q=0;q<4;q++) acc[mt][nt][q]=0.f;

        for (int ch=0; ch<8; ch++) {
            int kc = ch*32;
#pragma unroll
            for (int l=0;l<2;l++) {
                int idx = tid + l*256;
                int row = idx>>3, q = (idx&7)*4;
                float4 v = *(const float4*)(x + (size_t)(tok0+row)*CC + kc + q);
                Xs[row][q]=v.x; Xs[row][q+1]=v.y; Xs[row][q+2]=v.z; Xs[row][q+3]=v.w;
                float4 w = *(const float4*)(src + (size_t)row*CC + kc + q);
                Bs[row][q]=w.x; Bs[row][q+1]=w.y; Bs[row][q+2]=w.z; Bs[row][q+3]=w.w;
            }
            __syncthreads();
#pragma unroll
            for (int kpb=0; kpb<16; kpb+=8) {
                uint32_t ah[2][4], al[2][4], bh[2][2], bl[2][2];
#pragma unroll
                for (int mt=0;mt<2;mt++) {
                    int m0 = wm*32 + mt*16 + gid;
                    int k0 = 2*(kpb+tig), k1 = 2*(kpb+tig+4);
                    pkhl(Xs[m0][k0],   Xs[m0][k0+1],   ah[mt][0], al[mt][0]);
                    pkhl(Xs[m0+8][k0], Xs[m0+8][k0+1], ah[mt][1], al[mt][1]);
                    pkhl(Xs[m0][k1],   Xs[m0][k1+1],   ah[mt][2], al[mt][2]);
                    pkhl(Xs[m0+8][k1], Xs[m0+8][k1+1], ah[mt][3], al[mt][3]);
                }
#pragma unroll
                for (int nt=0;nt<2;nt++) {
                    int nl = wn*16 + nt*8 + gid;
                    int k0 = 2*(kpb+tig), k1 = 2*(kpb+tig+4);
                    pkhl(Bs[nl][k0], Bs[nl][k0+1], bh[nt][0], bl[nt][0]);
                    pkhl(Bs[nl][k1], Bs[nl][k1+1], bh[nt][1], bl[nt][1]);
                }
#pragma unroll
                for (int mt=0;mt<2;mt++)
#pragma unroll
                    for (int nt=0;nt<2;nt++) {
                        mma16bf(acc[mt][nt], ah[mt], bh[nt]);
                        mma16bf(acc[mt][nt], ah[mt], bl[nt]);
                        mma16bf(acc[mt][nt], al[mt], bh[nt]);
                    }
            }
            __syncthreads();
        }
#pragma unroll
        for (int mt=0;mt<2;mt++)
#pragma unroll
            for (int nt=0;nt<2;nt++) {
                int col = colgrp*64 + wn*16 + nt*8 + 2*tig;
#pragma unroll
                for (int rr=0;rr<2;rr++) {
                    int tok = tok0 + wm*32 + mt*16 + gid + rr*8;
                    g_Y[(size_t)tok*CC + col]   = acc[mt][nt][rr*2];
                    g_Y[(size_t)tok*CC + col+1] = acc[mt][nt][rr*2+1];
                }
            }
    }
}

// ================= phase 2: S0 (plain bf16) | xG bf16-hilo + softmax + binning =================
__global__ void __launch_bounds__(256) k_big2(const float* __restrict__ x,
                                              const float* __restrict__ u) {
    __shared__ __align__(16) char smp[36352];
    int b = blockIdx.x;
    int tid=threadIdx.x, warp=tid>>5, lane=tid&31, gid=lane>>2, tig=lane&3;
    int wm = warp>>2, wn = warp&3;

    if (b < 128) {
        // ---- mode 0: S0 partial from X@M, plain bf16 (loss-only) ----
        uint32_t (*Xpk)[68] = (uint32_t (*)[68])smp;
        uint32_t (*Mpk)[68] = (uint32_t (*)[68])(smp + 4352);
        float* red = (float*)(smp + 8704);
        int tok0 = (b>>2)*64;
        int colgrp = b&3;
        const float* src = g_M + (size_t)colgrp*64*CC;
        float acc[2][2][4];
#pragma unroll
        for (int mt=0;mt<2;mt++)
#pragma unroll
            for (int nt=0;nt<2;nt++)
#pragma unroll
                for (int q=0;q<4;q++) acc[mt][nt][q]=0.f;

        for (int ch=0; ch<8; ch++) {
            int kc = ch*32;
#pragma unroll
            for (int l=0;l<2;l++) {
                int idx = tid + l*256;
                int row = idx>>3, q = (idx&7)*4;
                float4 v = *(const float4*)(x + (size_t)(tok0+row)*CC + kc + q);
                Xpk[q>>1][row]     = pk2(v.x, v.y);
                Xpk[(q>>1)+1][row] = pk2(v.z, v.w);
            }
            {
                int row = tid>>2, q = (tid&3)*8;
                float4 v = *(const float4*)(src + (size_t)row*CC + kc + q);
                Mpk[q>>1][row]     = pk2(v.x, v.y);
                Mpk[(q>>1)+1][row] = pk2(v.z, v.w);
                float4 w = *(const float4*)(src + (size_t)row*CC + kc + q + 4);
                Mpk[(q>>1)+2][row] = pk2(w.x, w.y);
                Mpk[(q>>1)+3][row] = pk2(w.z, w.w);
            }
            __syncthreads();
#pragma unroll
            for (int kpb=0; kpb<16; kpb+=8) {
                uint32_t a[2][4], bv[2][2];
#pragma unroll
                for (int mt=0;mt<2;mt++) {
                    int m0 = wm*32 + mt*16 + gid;
                    a[mt][0]=Xpk[kpb+tig][m0];
                    a[mt][1]=Xpk[kpb+tig][m0+8];
                    a[mt][2]=Xpk[kpb+tig+4][m0];
                    a[mt][3]=Xpk[kpb+tig+4][m0+8];
                }
#pragma unroll
                for (int nt=0;nt<2;nt++) {
                    int nl = wn*16 + nt*8 + gid;
                    bv[nt][0]=Mpk[kpb+tig][nl];
                    bv[nt][1]=Mpk[kpb+tig+4][nl];
                }
#pragma unroll
                for (int mt=0;mt<2;mt++)
#pragma unroll
                    for (int nt=0;nt<2;nt++) mma16bf(acc[mt][nt], a[mt], bv[nt]);
            }
            __syncthreads();
        }
        float s0 = 0.f;
#pragma unroll
        for (int mt=0;mt<2;mt++)
#pragma unroll
            for (int nt=0;nt<2;nt++) {
                int col = colgrp*64 + wn*16 + nt*8 + 2*tig;
#pragma unroll
                for (int rr=0;rr<2;rr++) {
                    int tok = tok0 + wm*32 + mt*16 + gid + rr*8;
                    s0 += acc[mt][nt][rr*2]   * x[(size_t)tok*CC + col];
                    s0 += acc[mt][nt][rr*2+1] * x[(size_t)tok*CC + col+1];
                }
            }
        red[tid] = s0; __syncthreads();
        for (int s=128;s>=1;s>>=1) { if (tid<s) red[tid]+=red[tid+s]; __syncthreads(); }
        if (tid == 0) atomicAdd(&g_accd[0], (double)red[0]);
        return;
    }
    // ---- mode 1: xG = X@G^T, bf16 hi/lo (routing), + softmax/S1a/binning ----
    uint32_t (*Xph)[68] = (uint32_t (*)[68])smp;            // 4352
    uint32_t (*Xpl)[68] = (uint32_t (*)[68])(smp + 4352);   // 4352
    uint32_t (*Gph)[68] = (uint32_t (*)[68])(smp + 8704);   // 4352
    uint32_t (*Gpl)[68] = (uint32_t (*)[68])(smp + 13056);  // 4352
    float (*xgs)[68] = (float (*)[68])(smp + 17408);        // 17408
    int tok0 = (b-128)*64;
    float acc[2][2][4];
#pragma unroll
    for (int mt=0;mt<2;mt++)
#pragma unroll
        for (int nt=0;nt<2;nt++)
#pragma unroll
            for (int q=0;q<4;q++) acc[mt][nt][q]=0.f;

    for (int ch=0; ch<8; ch++) {
        int kc = ch*32;
#pragma unroll
        for (int l=0;l<2;l++) {
            int idx = tid + l*256;
            int row = idx>>3, q = (idx&7)*4;
            float4 v = *(const float4*)(x + (size_t)(tok0+row)*CC + kc + q);
            pkhl(v.x, v.y, Xph[q>>1][row],     Xpl[q>>1][row]);
            pkhl(v.z, v.w, Xph[(q>>1)+1][row], Xpl[(q>>1)+1][row]);
            float4 w = *(const float4*)(g_G + (size_t)row*CC + kc + q);
            pkhl(w.x, w.y, Gph[q>>1][row],     Gpl[q>>1][row]);
            pkhl(w.z, w.w, Gph[(q>>1)+1][row], Gpl[(q>>1)+1][row]);
        }
        __syncthreads();
#pragma unroll
        for (int kpb=0; kpb<16; kpb+=8) {
            uint32_t ah[2][4], al[2][4], bh[2][2], bl[2][2];
#pragma unroll
            for (int mt=0;mt<2;mt++) {
                int m0 = wm*32 + mt*16 + gid;
                ah[mt][0]=Xph[kpb+tig][m0];   al[mt][0]=Xpl[kpb+tig][m0];
                ah[mt][1]=Xph[kpb+tig][m0+8]; al[mt][1]=Xpl[kpb+tig][m0+8];
                ah[mt][2]=Xph[kpb+tig+4][m0];   al[mt][2]=Xpl[kpb+tig+4][m0];
                ah[mt][3]=Xph[kpb+tig+4][m0+8]; al[mt][3]=Xpl[kpb+tig+4][m0+8];
            }
#pragma unroll
            for (int nt=0;nt<2;nt++) {
                int nl = wn*16 + nt*8 + gid;
                bh[nt][0]=Gph[kpb+tig][nl];   bh[nt][1]=Gph[kpb+tig+4][nl];
                bl[nt][0]=Gpl[kpb+tig][nl];   bl[nt][1]=Gpl[kpb+tig+4][nl];
            }
#pragma unroll
            for (int mt=0;mt<2;mt++)
#pragma unroll
                for (int nt=0;nt<2;nt++) {
                    mma16bf(acc[mt][nt], ah[mt], bh[nt]);
                    mma16bf(acc[mt][nt], ah[mt], bl[nt]);
                    mma16bf(acc[mt][nt], al[mt], bh[nt]);
                }
        }
        __syncthreads();
    }
#pragma unroll
    for (int mt=0;mt<2;mt++)
#pragma unroll
        for (int nt=0;nt<2;nt++) {
            int col = wn*16 + nt*8 + 2*tig;
#pragma unroll
            for (int rr=0;rr<2;rr++) {
                int lt = wm*32 + mt*16 + gid + rr*8;
                xgs[lt][col]   = acc[mt][nt][rr*2];
                xgs[lt][col+1] = acc[mt][nt][rr*2+1];
            }
        }
    __syncthreads();
    float cn0 = (float)g_cnormd[lane], cn1 = (float)g_cnormd[lane+32];
    float bc0 = (float)g_bcd[lane],    bc1 = (float)g_bcd[lane+32];
    float s1acc = 0.f;
    for (int k=0;k<8;k++) {
        int lt = warp*8 + k;
        size_t n = tok0 + lt;
        float xg0 = xgs[lt][lane]    + bc0;
        float xg1 = xgs[lt][lane+32] + bc1;
        float l0 = 2.f*xg0 - cn0 - logf(-logf(u[n*NE+lane]));
        float l1 = 2.f*xg1 - cn1 - logf(-logf(u[n*NE+lane+32]));
        float m = fmaxf(l0, l1);
#pragma unroll
        for (int o=16;o>=1;o>>=1) m = fmaxf(m, __shfl_xor_sync(0xffffffffu, m, o));
        float ex0 = expf(l0 - m), ex1 = expf(l1 - m);
        float S = ex0 + ex1;
#pragma unroll
        for (int o=16;o>=1;o>>=1) S += __shfl_xor_sync(0xffffffffu, S, o);
        float r0 = ex0 / S, r1 = ex1 / S;
        g_resp[n*NE+lane]    = r0;
        g_resp[n*NE+lane+32] = r1;
        float s1 = r0*xg0 + r1*xg1;
#pragma unroll
        for (int o=16;o>=1;o>>=1) s1 += __shfl_xor_sync(0xffffffffu, s1, o);
        if (lane == 0) s1acc += s1;
        if (r0 > 1e-9f) {
            int p = atomicAdd(&g_cnt[lane], 1);
            g_tokn[lane*NN+p] = (int)n; g_tokr[lane*NN+p] = r0;
        }
        if (r1 > 1e-9f) {
            int p = atomicAdd(&g_cnt[lane+32], 1);
            g_tokn[(lane+32)*NN+p] = (int)n; g_tokr[(lane+32)*NN+p] = r1;
        }
    }
    if (lane == 0) atomicAdd(&g_accd[1], (double)s1acc);
}

// ================= A=R^T X (plain), Q=R^T R (hi/lo), s, xsum  (32 tokens/blk) =================
__global__ void __launch_bounds__(256) k_RX(const float* __restrict__ x) {
    __shared__ float Rs[32][68];
    __shared__ float Xs[32][260];
    int tid=threadIdx.x, warp=tid>>5, lane=tid&31, gid=lane>>2, tig=lane&3;
    int nb = blockIdx.x * 32;
    float accA[4][4][4], accQ[4][4];
#pragma unroll
    for (int mt=0;mt<4;mt++) {
#pragma unroll
        for (int nt=0;nt<4;nt++)
#pragma unroll
            for (int q=0;q<4;q++) accA[mt][nt][q]=0.f;
#pragma unroll
        for (int q=0;q<4;q++) accQ[mt][q]=0.f;
    }
    float sp=0.f, xsacc=0.f;

#pragma unroll
    for (int l=0;l<8;l++) {
        int idx = tid + l*256;
        int row = idx>>6, e2 = idx&63;
        Rs[row][e2] = g_resp[(size_t)(nb+row)*NE + e2];
    }
#pragma unroll
    for (int l=0;l<8;l++) {
        int idx = tid + l*256;
        int row = idx>>6, q = (idx&63)*4;
        float4 v = *(const float4*)(x + (size_t)(nb+row)*CC + q);
        Xs[row][q]=v.x; Xs[row][q+1]=v.y; Xs[row][q+2]=v.z; Xs[row][q+3]=v.w;
    }
    __syncthreads();
    if (tid < 64) {
        for (int k=0;k<32;k++) sp += Rs[k][tid];
    }
    for (int k=0;k<32;k++) xsacc += Xs[k][tid];
#pragma unroll
    for (int k8=0;k8<4;k8++) {
        int kb = k8*8;
        uint32_t am[4][4], amh[4][4], aml[4][4];
#pragma unroll
        for (int mt=0;mt<4;mt++) {
            int m0 = mt*16;
            float v0 = Rs[kb+tig][m0+gid],   v1 = Rs[kb+tig][m0+gid+8];
            float v2 = Rs[kb+tig+4][m0+gid], v3 = Rs[kb+tig+4][m0+gid+8];
            am[mt][0]=fb(v0); am[mt][1]=fb(v1); am[mt][2]=fb(v2); am[mt][3]=fb(v3);
            hilo(v0, amh[mt][0], aml[mt][0]); hilo(v1, amh[mt][1], aml[mt][1]);
            hilo(v2, amh[mt][2], aml[mt][2]); hilo(v3, amh[mt][3], aml[mt][3]);
        }
#pragma unroll
        for (int nt=0;nt<4;nt++) {
            int c = warp*32 + nt*8 + gid;
            uint32_t bx[2] = { fb(Xs[kb+tig][c]), fb(Xs[kb+tig+4][c]) };
#pragma unroll
            for (int mt=0;mt<4;mt++) mma8(accA[mt][nt], am[mt], bx);
        }
        {
            int eq = warp*8 + gid;
            uint32_t bqh[2], bql[2];
            hilo(Rs[kb+tig][eq],   bqh[0], bql[0]);
            hilo(Rs[kb+tig+4][eq], bqh[1], bql[1]);
#pragma unroll
            for (int mt=0;mt<4;mt++) {
                mma8(accQ[mt], amh[mt], bqh);
                mma8(accQ[mt], amh[mt], bql);
                mma8(accQ[mt], aml[mt], bqh);
            }
        }
    }
#pragma unroll
    for (int mt=0;mt<4;mt++) {
#pragma unroll
        for (int nt=0;nt<4;nt++) {
            int e = mt*16 + gid;
            int c = warp*32 + nt*8 + 2*tig;
            atomicAdd(&g_A[e*CC+c],        accA[mt][nt][0]);
            atomicAdd(&g_A[e*CC+c+1],      accA[mt][nt][1]);
            atomicAdd(&g_A[(e+8)*CC+c],    accA[mt][nt][2]);
            atomicAdd(&g_A[(e+8)*CC+c+1],  accA[mt][nt][3]);
        }
        int e = mt*16 + gid;
        int eq = warp*8 + 2*tig;
        atomicAdd(&g_Q[e*NE+eq],       accQ[mt][0]);
        atomicAdd(&g_Q[e*NE+eq+1],     accQ[mt][1]);
        atomicAdd(&g_Q[(e+8)*NE+eq],   accQ[mt][2]);
        atomicAdd(&g_Q[(e+8)*NE+eq+1], accQ[mt][3]);
    }
    if (tid < 64) atomicAdd(&g_s[tid], sp);
    atomicAdd(&g_xsum[tid], xsacc);
}

// ================= Cnew bf16 (512 blks) | loss contractions (64 blks) =================
__global__ void __launch_bounds__(256) k_cnew(const float* __restrict__ W,
                                              const float* __restrict__ cents,
                                              const float* __restrict__ bvec) {
    int tid=threadIdx.x, warp=tid>>5, lane=tid&31, gid=lane>>2, tig=lane&3;
    if (blockIdx.x >= 512) {
        int e = blockIdx.x - 512;
        __shared__ float As[256];
        __shared__ float red[256];
        As[tid] = g_A[e*CC + tid];
        __syncthreads();
        float uv = 0.f;
        for (int e2=0;e2<NE;e2++) uv += g_Q[e*NE+e2] * g_A[e2*CC + tid];
        float am = 0.f;
        for (int c=0;c<CC;c++) am += As[c] * g_M[c*CC + tid];
        float a = As[tid];
        float ge = g_G[e*CC + tid];
        float wtb = g_Wtb[tid];

        float r1, r2, r3, r4, r5, r6;
        red[tid] = am*a; __syncthreads();
        for (int s=128;s>=1;s>>=1) { if (tid<s) red[tid]+=red[tid+s]; __syncthreads(); }
        r1 = red[0]; __syncthreads();
        red[tid] = a*wtb; __syncthreads();
        for (int s=128;s>=1;s>>=1) { if (tid<s) red[tid]+=red[tid+s]; __syncthreads(); }
        r2 = red[0]; __syncthreads();
        red[tid] = ge*uv; __syncthreads();
        for (int s=128;s>=1;s>>=1) { if (tid<s) red[tid]+=red[tid+s]; __syncthreads(); }
        r3 = red[0]; __syncthreads();
        red[tid] = am*uv; __syncthreads();
        for (int s=128;s>=1;s>>=1) { if (tid<s) red[tid]+=red[tid+s]; __syncthreads(); }
        r4 = red[0]; __syncthreads();
        red[tid] = (tid < NE) ? g_Q[e*NE+tid]*g_s[tid] : 0.f; __syncthreads();
        for (int s=128;s>=1;s>>=1) { if (tid<s) red[tid]+=red[tid+s]; __syncthreads(); }
        r5 = red[0]; __syncthreads();
        red[tid] = (tid < NE) ? g_CG[e*NE+tid]*g_Q[e*NE+tid] : 0.f; __syncthreads();
        for (int s=128;s>=1;s>>=1) { if (tid<s) red[tid]+=red[tid+s]; __syncthreads(); }
        r6 = red[0]; __syncthreads();

        if (tid == 0) {
            double se = (double)g_s[e];
            double bb = g_bbd;
            double bce = g_bcd[e];
            double d = 0.999, gam = (double)GAMv;
            double p_e = (double)r1 + 2.0*se*(double)r2 + bb*se*se;
            double quad_e = d*d*(double)r6
                          + 2.0*d*gam*((double)r3 + bce*(double)r5)
                          + gam*gam*((double)r4 + 2.0*(double)r2*(double)r5 + bb*se*(double)r5);
            atomicAdd(&g_accd[2], p_e);
            atomicAdd(&g_accd[3], quad_e);
        }
        if (e == 0) {
            red[tid] = 2.f*g_xsum[tid]*g_Wtb[tid]; __syncthreads();
            for (int s=128;s>=1;s>>=1) { if (tid<s) red[tid]+=red[tid+s]; __syncthreads(); }
            if (tid == 0) atomicAdd(&g_accd[0], (double)red[0] + (double)NN * g_bbd);
        }
        return;
    }
    // ---- Cnew = decay*Cents + gam*(A@W^T + s b^T), bf16 m16n8k16 ----
    __shared__ uint32_t Apk[16][68];
    __shared__ uint32_t Wpk[16][132];
    __shared__ float ss[64];
    int d0 = blockIdx.x * 128;
    if (tid < 64) ss[tid] = g_s[tid];
    float acc[4][2][4];
#pragma unroll
    for (int mt=0;mt<4;mt++)
#pragma unroll
        for (int nt=0;nt<2;nt++)
#pragma unroll
            for (int q=0;q<4;q++) acc[mt][nt][q]=0.f;

    for (int ch=0; ch<8; ch++) {
        int kc = ch*32;
#pragma unroll
        for (int l=0;l<2;l++) {
            int idx = tid + l*256;
            int e = idx>>3, q = (idx&7)*4;
            float4 v = *(const float4*)(g_A + (size_t)e*CC + kc + q);
            Apk[q>>1][e]     = pk2(v.x, v.y);
            Apk[(q>>1)+1][e] = pk2(v.z, v.w);
        }
#pragma unroll
        for (int l=0;l<4;l++) {
            int idx = tid + l*256;
            int row = idx>>3, q = (idx&7)*4;
            float4 v = *(const float4*)(W + (size_t)(d0+row)*CC + kc + q);
            Wpk[q>>1][row]     = pk2(v.x, v.y);
            Wpk[(q>>1)+1][row] = pk2(v.z, v.w);
        }
        __syncthreads();
#pragma unroll
        for (int kpb=0; kpb<16; kpb+=8) {
            uint32_t a[4][4], b[2][2];
#pragma unroll
            for (int mt=0;mt<4;mt++) {
                int e = mt*16 + gid;
                a[mt][0]=Apk[kpb+tig][e];
                a[mt][1]=Apk[kpb+tig][e+8];
                a[mt][2]=Apk[kpb+tig+4][e];
                a[mt][3]=Apk[kpb+tig+4][e+8];
            }
#pragma unroll
            for (int nt=0;nt<2;nt++) {
                int dl = warp*16 + nt*8 + gid;
                b[nt][0]=Wpk[kpb+tig][dl];
                b[nt][1]=Wpk[kpb+tig+4][dl];
            }
#pragma unroll
            for (int mt=0;mt<4;mt++)
#pragma unroll
                for (int nt=0;nt<2;nt++) mma16bf(acc[mt][nt], a[mt], b[nt]);
        }
        __syncthreads();
    }
#pragma unroll
    for (int mt=0;mt<4;mt++)
#pragma unroll
        for (int nt=0;nt<2;nt++) {
            int e = mt*16 + gid;
            int d = d0 + warp*16 + nt*8 + 2*tig;
            float b0 = bvec[d], b1 = bvec[d+1];
            g_Cnew[(size_t)e*DD+d]       = DECAYv*cents[(size_t)e*DD+d]       + GAMv*(acc[mt][nt][0] + ss[e]*b0);
            g_Cnew[(size_t)e*DD+d+1]     = DECAYv*cents[(size_t)e*DD+d+1]     + GAMv*(acc[mt][nt][1] + ss[e]*b1);
            g_Cnew[(size_t)(e+8)*DD+d]   = DECAYv*cents[(size_t)(e+8)*DD+d]   + GAMv*(acc[mt][nt][2] + ss[e+8]*b0);
            g_Cnew[(size_t)(e+8)*DD+d+1] = DECAYv*cents[(size_t)(e+8)*DD+d+1] + GAMv*(acc[mt][nt][3] + ss[e+8]*b1);
        }
}

// ================= binned output GEMM (bf16 hi/lo), persistent 8 slots/expert =================
__global__ void __launch_bounds__(256) k_out(float* __restrict__ out) {
    __shared__ __align__(16) char smp[70400];
    int b = blockIdx.x;
    int tid=threadIdx.x, warp=tid>>5, lane=tid&31, gid=lane>>2, tig=lane&3;
    int e = b & 63;
    int cnt = g_cnt[e];
    float (*ys)[260] = (float (*)[260])smp;
    float (*Cw)[36]  = (float (*)[36])(smp + 33280);
    int* stok        = (int*)(smp + 33280 + 36864);
    int wm = warp>>2, wn = warp&3;

    for (int a0 = (b >> 6) * 32; a0 < cnt; a0 += 256) {
#pragma unroll
        for (int l=0;l<8;l++) {
            int idx = tid + l*256;
            int row = idx >> 6, q = idx & 63;
            int aa = a0 + row;
            float r = 0.f; int n = 0;
            float4 v = make_float4(0.f,0.f,0.f,0.f);
            if (aa < cnt) {
                n = g_tokn[e*NN+aa]; r = g_tokr[e*NN+aa];
                v = *(const float4*)(g_Y + (size_t)n*CC + q*4);
            }
            ys[row][q*4]=r*v.x; ys[row][q*4+1]=r*v.y; ys[row][q*4+2]=r*v.z; ys[row][q*4+3]=r*v.w;
            if (q == 0) stok[row] = n;
        }
        __syncthreads();
        float acc[8][4];
#pragma unroll
        for (int nt=0;nt<8;nt++)
#pragma unroll
            for (int q=0;q<4;q++) acc[nt][q]=0.f;

        for (int ch=0; ch<8; ch++) {
            int kc = ch*32;
#pragma unroll
            for (int l=0;l<8;l++) {
                int idx = tid + l*256;
                int row = idx >> 3, q = (idx & 7)*4;
                float4 v = *(const float4*)(g_Cnew + (size_t)e*DD + (size_t)row*CC + kc + q);
                Cw[row][q]=v.x; Cw[row][q+1]=v.y; Cw[row][q+2]=v.z; Cw[row][q+3]=v.w;
            }
            __syncthreads();
#pragma unroll
            for (int kpb=0; kpb<16; kpb+=8) {
                uint32_t ah[4], al[4];
                int m0 = wm*16 + gid;
                int k0 = 2*(kpb+tig), k1 = 2*(kpb+tig+4);
                pkhl(ys[m0][kc+k0],   ys[m0][kc+k0+1],   ah[0], al[0]);
                pkhl(ys[m0+8][kc+k0], ys[m0+8][kc+k0+1], ah[1], al[1]);
                pkhl(ys[m0][kc+k1],   ys[m0][kc+k1+1],   ah[2], al[2]);
                pkhl(ys[m0+8][kc+k1], ys[m0+8][kc+k1+1], ah[3], al[3]);
#pragma unroll
                for (int nt=0;nt<8;nt++) {
                    int nc = wn*64 + nt*8 + gid;
                    uint32_t bh[2], bl[2];
                    pkhl(Cw[nc][k0], Cw[nc][k0+1], bh[0], bl[0]);
                    pkhl(Cw[nc][k1], Cw[nc][k1+1], bh[1], bl[1]);
                    mma16bf(acc[nt], ah, bh);
                    mma16bf(acc[nt], ah, bl);
                    mma16bf(acc[nt], al, bh);
                }
            }
            __syncthreads();
        }
        int t0 = wm*16 + gid;
        int r0 = stok[t0], r1 = stok[t0+8];
#pragma unroll
        for (int nt=0;nt<8;nt++) {
            int i = wn*64 + nt*8 + 2*tig;
            atomicAdd(out + (size_t)r0*ROUT + i,   acc[nt][0]);
            atomicAdd(out + (size_t)r0*ROUT + i+1, acc[nt][1]);
            atomicAdd(out + (size_t)r1*ROUT + i,   acc[nt][2]);
            atomicAdd(out + (size_t)r1*ROUT + i+1, acc[nt][3]);
        }
        __syncthreads();
    }
}

// ================= final: bias | loss scalar =================
__global__ void k_fin(float* __restrict__ out, const float* __restrict__ pwB, int out_size) {
    int b = blockIdx.x, tid = threadIdx.x;
    if (b < NN) {
        out[(size_t)b*ROUT + tid] += pwB[tid];
        return;
    }
    double S1 = 0.999*g_accd[1] + (double)GAMv*g_accd[2];
    double loss = 0.25*(g_accd[0] - 2.0*S1 + g_accd[3]) / ((double)NN * (double)DD);
    float lf = (float)loss;
    for (int i = NN*ROUT + tid; i < out_size; i += 256) out[i] = lf;
}

extern "C" void kernel_launch(void* const* d_in, const int* in_sizes, int n_in,
                              void* d_out, int out_size) {
    const float* x     = (const float*)d_in[0];
    const float* u     = (const float*)d_in[1];
    const float* W     = (const float*)d_in[2];
    const float* bvec  = (const float*)d_in[3];
    const float* pw1   = (const float*)d_in[4];
    const float* pwB   = (const float*)d_in[5];
    const float* cents = (const float*)d_in[6];
    float* out = (float*)d_out;

    k_zero<<<2048, 256>>>(out);
    k_p1<<<512, 256>>>(W, cents, bvec, x, pw1);
    k_big2<<<160, 256>>>(x, u);
    k_RX<<<64, 256>>>(x);
    k_cnew<<<576, 256>>>(W, cents, bvec);
    k_out<<<512, 256>>>(out);
    k_fin<<<NN + 1, 256>>>(out, pwB, out_size);
}